// round 1
// baseline (speedup 1.0000x reference)
#include <cuda_runtime.h>

// ---------------------------------------------------------------------------
// SimpleModalityUntiedAttention: B=2 S=2048 D=1024 H=16 HD=64 M=2 E=1024
// Round 1: correct fp32 SIMT implementation, tiled GEMMs, 2-pass flash
// attention with in-block head-averaged attention-weight accumulation.
// ---------------------------------------------------------------------------

namespace {
constexpr int kB  = 2;
constexpr int kS  = 2048;
constexpr int kD  = 1024;
constexpr int kH  = 16;
constexpr int kHD = 64;
constexpr int kM  = 2;
constexpr int kE  = 1024;
constexpr int kNR = kB * kS;   // 4096 token rows
constexpr float kEps = 1e-5f;
}

// Scratch (static device globals: allocation-free contract)
__device__ float g_q[kNR * kE];
__device__ float g_k[kNR * kE];
__device__ float g_v[kNR * kE];
__device__ float g_ctx[kNR * kE];
__device__ float g_o[kNR * kD];
__device__ float g_ml[kB * kH * kS * 2];   // (max, sumexp) per (b,h,q)

// ---------------------------------------------------------------------------
// Tile loaders: 64x64 fp32 tile from a row-major matrix with row stride kE.
// _T stores transposed dst[d][r] (for QK^T inner products), _N natural.
// Pitch 68 keeps float4 alignment (68*4=272 = 16*17) and spreads banks.
// ---------------------------------------------------------------------------
__device__ __forceinline__ void load_tile_T(float (*dst)[68], const float* src, int tid) {
#pragma unroll
    for (int rep = 0; rep < 4; ++rep) {
        int idx = tid + rep * 256;
        int r   = idx >> 4;
        int c4  = (idx & 15) << 2;
        float4 v = *(const float4*)(src + (size_t)r * kE + c4);
        dst[c4 + 0][r] = v.x;
        dst[c4 + 1][r] = v.y;
        dst[c4 + 2][r] = v.z;
        dst[c4 + 3][r] = v.w;
    }
}

__device__ __forceinline__ void load_tile_N(float (*dst)[68], const float* src, int tid) {
#pragma unroll
    for (int rep = 0; rep < 4; ++rep) {
        int idx = tid + rep * 256;
        int r   = idx >> 4;
        int c4  = (idx & 15) << 2;
        float4 v = *(const float4*)(src + (size_t)r * kE + c4);
        *(float4*)&dst[r][c4] = v;
    }
}

// ---------------------------------------------------------------------------
// K1: QKV projection (both modalities; selected rows written), fused per-head
// RMSNorm for q/k in the epilogue (tile N = 64 = HD aligns with heads).
// grid.z = m*3 + which (which: 0=q, 1=k, 2=v)
// ---------------------------------------------------------------------------
__global__ __launch_bounds__(256) void k_qkv(
    const float* __restrict__ x,
    const float* __restrict__ Wq, const float* __restrict__ Wk,
    const float* __restrict__ Wv,
    const int* __restrict__ mod_ids,
    const float* __restrict__ qn_w, const float* __restrict__ kn_w)
{
    const int z = blockIdx.z;
    const int m = z / 3;
    const int which = z % 3;
    const float* W = ((which == 0) ? Wq : (which == 1) ? Wk : Wv) + (size_t)m * kD * kE;
    float* Cout = (which == 0) ? g_q : (which == 1) ? g_k : g_v;

    const int tid  = threadIdx.x;
    const int ty   = tid >> 4, tx = tid & 15;
    const int rows = blockIdx.y * 64;
    const int cols = blockIdx.x * 64;

    __shared__ float As[16][64];
    __shared__ float Bs[16][64];

    float acc[4][4] = {};

    const int ar = tid >> 2;
    const int ak = (tid & 3) << 2;
    const int bk = tid >> 4;
    const int bc = (tid & 15) << 2;

    const float* aptr = x + (size_t)(rows + ar) * kD + ak;
    const float* bptr = W + (size_t)bk * kE + cols + bc;

    for (int k0 = 0; k0 < kD; k0 += 16) {
        float4 av = *(const float4*)(aptr + k0);
        float4 bv = *(const float4*)(bptr + (size_t)k0 * kE);
        __syncthreads();
        As[ak + 0][ar] = av.x;
        As[ak + 1][ar] = av.y;
        As[ak + 2][ar] = av.z;
        As[ak + 3][ar] = av.w;
        *(float4*)&Bs[bk][bc] = bv;
        __syncthreads();
#pragma unroll
        for (int kk = 0; kk < 16; ++kk) {
            float4 a4 = *(const float4*)&As[kk][ty << 2];
            float4 b4 = *(const float4*)&Bs[kk][tx << 2];
            float aa[4] = {a4.x, a4.y, a4.z, a4.w};
            float bb[4] = {b4.x, b4.y, b4.z, b4.w};
#pragma unroll
            for (int i = 0; i < 4; ++i)
#pragma unroll
                for (int j = 0; j < 4; ++j)
                    acc[i][j] = fmaf(aa[i], bb[j], acc[i][j]);
        }
    }

    int mid[4];
#pragma unroll
    for (int i = 0; i < 4; ++i) mid[i] = mod_ids[rows + (ty << 2) + i];

    if (which < 2) {
        // per-head RMSNorm: tile columns are exactly one head's 64 dims
        const float* wn = ((which == 0) ? qn_w : kn_w) + m * kHD;
        float w4[4];
#pragma unroll
        for (int j = 0; j < 4; ++j) w4[j] = wn[(tx << 2) + j];
#pragma unroll
        for (int i = 0; i < 4; ++i) {
            float ss = acc[i][0] * acc[i][0] + acc[i][1] * acc[i][1] +
                       acc[i][2] * acc[i][2] + acc[i][3] * acc[i][3];
#pragma unroll
            for (int off = 1; off < 16; off <<= 1)
                ss += __shfl_xor_sync(0xffffffffu, ss, off);
            float sc = rsqrtf(ss * (1.0f / 64.0f) + kEps);
            if (mid[i] == m) {
                float4 o;
                o.x = acc[i][0] * sc * w4[0];
                o.y = acc[i][1] * sc * w4[1];
                o.z = acc[i][2] * sc * w4[2];
                o.w = acc[i][3] * sc * w4[3];
                *(float4*)(Cout + (size_t)(rows + (ty << 2) + i) * kE + cols + (tx << 2)) = o;
            }
        }
    } else {
#pragma unroll
        for (int i = 0; i < 4; ++i) {
            if (mid[i] == m) {
                float4 o = {acc[i][0], acc[i][1], acc[i][2], acc[i][3]};
                *(float4*)(Cout + (size_t)(rows + (ty << 2) + i) * kE + cols + (tx << 2)) = o;
            }
        }
    }
}

// ---------------------------------------------------------------------------
// K2: softmax stats (row max m, sumexp l) per (b,h,q). Flash pass 1.
// grid = (S/64, B*H), block 256 (16x16 threads, 4x4 microtiles)
// ---------------------------------------------------------------------------
__global__ __launch_bounds__(256) void k_stats(const float* __restrict__ mask)
{
    const int bh = blockIdx.y;
    const int b = bh >> 4, h = bh & 15;
    const int qbase = blockIdx.x * 64;
    const int tid = threadIdx.x;
    const int ty = tid >> 4, tx = tid & 15;

    __shared__ float Qs[64][68];
    __shared__ float Ks[64][68];

    load_tile_T(Qs, g_q + ((size_t)(b * kS + qbase)) * kE + h * kHD, tid);

    float mr[4], lr[4];
#pragma unroll
    for (int i = 0; i < 4; ++i) { mr[i] = -3e38f; lr[i] = 0.0f; }

    const int qr0 = qbase + (ty << 2);

    for (int kb = 0; kb < kS; kb += 64) {
        __syncthreads();
        load_tile_T(Ks, g_k + ((size_t)(b * kS + kb)) * kE + h * kHD, tid);
        __syncthreads();

        float s[4][4] = {};
#pragma unroll
        for (int d = 0; d < 64; ++d) {
            float4 a4 = *(const float4*)&Qs[d][ty << 2];
            float4 b4 = *(const float4*)&Ks[d][tx << 2];
            float aa[4] = {a4.x, a4.y, a4.z, a4.w};
            float bb[4] = {b4.x, b4.y, b4.z, b4.w};
#pragma unroll
            for (int i = 0; i < 4; ++i)
#pragma unroll
                for (int j = 0; j < 4; ++j)
                    s[i][j] = fmaf(aa[i], bb[j], s[i][j]);
        }

#pragma unroll
        for (int i = 0; i < 4; ++i) {
            float4 mv = *(const float4*)(mask + (size_t)(qr0 + i) * kS + kb + (tx << 2));
            float sv0 = fmaf(s[i][0], 0.125f, mv.x);
            float sv1 = fmaf(s[i][1], 0.125f, mv.y);
            float sv2 = fmaf(s[i][2], 0.125f, mv.z);
            float sv3 = fmaf(s[i][3], 0.125f, mv.w);
            float tm = fmaxf(fmaxf(sv0, sv1), fmaxf(sv2, sv3));
#pragma unroll
            for (int off = 1; off < 16; off <<= 1)
                tm = fmaxf(tm, __shfl_xor_sync(0xffffffffu, tm, off));
            float nm = fmaxf(mr[i], tm);
            float corr = __expf(mr[i] - nm);
            float es = __expf(sv0 - nm) + __expf(sv1 - nm) +
                       __expf(sv2 - nm) + __expf(sv3 - nm);
#pragma unroll
            for (int off = 1; off < 16; off <<= 1)
                es += __shfl_xor_sync(0xffffffffu, es, off);
            lr[i] = lr[i] * corr + es;
            mr[i] = nm;
        }
    }

    if (tx == 0) {
#pragma unroll
        for (int i = 0; i < 4; ++i) {
            g_ml[((size_t)bh * kS + qr0 + i) * 2 + 0] = mr[i];
            g_ml[((size_t)bh * kS + qr0 + i) * 2 + 1] = lr[i];
        }
    }
}

// ---------------------------------------------------------------------------
// K3: attn_weights[b,q,k] = (1/H) sum_h p[b,h,q,k]. One block owns a
// (b, q-tile, k-tile) patch and loops heads -> register accumulation, single
// store, no atomics, no [B,H,S,S] scratch.
// grid = (S/64, S/64, B), block 256
// ---------------------------------------------------------------------------
__global__ __launch_bounds__(256) void k_attnw(const float* __restrict__ mask,
                                               float* __restrict__ aw_out)
{
    const int b = blockIdx.z;
    const int qbase = blockIdx.y * 64;
    const int kbase = blockIdx.x * 64;
    const int tid = threadIdx.x;
    const int ty = tid >> 4, tx = tid & 15;
    const int qr0 = qbase + (ty << 2);

    __shared__ float Qs[64][68];
    __shared__ float Ks[64][68];

    float msk[4][4];
#pragma unroll
    for (int i = 0; i < 4; ++i) {
        float4 mv = *(const float4*)(mask + (size_t)(qr0 + i) * kS + kbase + (tx << 2));
        msk[i][0] = mv.x; msk[i][1] = mv.y; msk[i][2] = mv.z; msk[i][3] = mv.w;
    }

    float aw[4][4] = {};

    for (int h = 0; h < kH; ++h) {
        __syncthreads();
        load_tile_T(Qs, g_q + ((size_t)(b * kS + qbase)) * kE + h * kHD, tid);
        load_tile_T(Ks, g_k + ((size_t)(b * kS + kbase)) * kE + h * kHD, tid);
        __syncthreads();

        float mi[4], il[4];
#pragma unroll
        for (int i = 0; i < 4; ++i) {
            size_t mlidx = ((size_t)(b * kH + h) * kS + qr0 + i) * 2;
            mi[i] = g_ml[mlidx];
            il[i] = 1.0f / g_ml[mlidx + 1];
        }

        float s[4][4] = {};
#pragma unroll
        for (int d = 0; d < 64; ++d) {
            float4 a4 = *(const float4*)&Qs[d][ty << 2];
            float4 b4 = *(const float4*)&Ks[d][tx << 2];
            float aa[4] = {a4.x, a4.y, a4.z, a4.w};
            float bb[4] = {b4.x, b4.y, b4.z, b4.w};
#pragma unroll
            for (int i = 0; i < 4; ++i)
#pragma unroll
                for (int j = 0; j < 4; ++j)
                    s[i][j] = fmaf(aa[i], bb[j], s[i][j]);
        }

#pragma unroll
        for (int i = 0; i < 4; ++i)
#pragma unroll
            for (int j = 0; j < 4; ++j)
                aw[i][j] += __expf(fmaf(s[i][j], 0.125f, msk[i][j]) - mi[i]) * il[i];
    }

#pragma unroll
    for (int i = 0; i < 4; ++i) {
        float4 o;
        o.x = aw[i][0] * (1.0f / kH);
        o.y = aw[i][1] * (1.0f / kH);
        o.z = aw[i][2] * (1.0f / kH);
        o.w = aw[i][3] * (1.0f / kH);
        *(float4*)(aw_out + (size_t)b * kS * kS + (size_t)(qr0 + i) * kS + kbase + (tx << 2)) = o;
    }
}

// ---------------------------------------------------------------------------
// K4: ctx = P @ V, flash pass 2 (recompute scores, P in smem, P@V in smem).
// grid = (S/64, B*H), block 256, dynamic smem 3*64*68*4 = 52224 B
// ---------------------------------------------------------------------------
__global__ __launch_bounds__(256) void k_ctx(const float* __restrict__ mask)
{
    extern __shared__ float sh[];
    float (*Qs)[68]  = (float(*)[68])sh;
    float (*KVs)[68] = (float(*)[68])(sh + 64 * 68);
    float (*Ps)[68]  = (float(*)[68])(sh + 2 * 64 * 68);

    const int bh = blockIdx.y;
    const int b = bh >> 4, h = bh & 15;
    const int qbase = blockIdx.x * 64;
    const int tid = threadIdx.x;
    const int ty = tid >> 4, tx = tid & 15;
    const int qr0 = qbase + (ty << 2);

    load_tile_T(Qs, g_q + ((size_t)(b * kS + qbase)) * kE + h * kHD, tid);

    float mi[4], il[4];
#pragma unroll
    for (int i = 0; i < 4; ++i) {
        size_t mlidx = ((size_t)bh * kS + qr0 + i) * 2;
        mi[i] = g_ml[mlidx];
        il[i] = 1.0f / g_ml[mlidx + 1];
    }

    float cacc[4][4] = {};

    for (int kb = 0; kb < kS; kb += 64) {
        __syncthreads();  // prev iter's Ps/V reads done
        load_tile_T(KVs, g_k + ((size_t)(b * kS + kb)) * kE + h * kHD, tid);
        __syncthreads();

        float s[4][4] = {};
#pragma unroll
        for (int d = 0; d < 64; ++d) {
            float4 a4 = *(const float4*)&Qs[d][ty << 2];
            float4 b4 = *(const float4*)&KVs[d][tx << 2];
            float aa[4] = {a4.x, a4.y, a4.z, a4.w};
            float bb[4] = {b4.x, b4.y, b4.z, b4.w};
#pragma unroll
            for (int i = 0; i < 4; ++i)
#pragma unroll
                for (int j = 0; j < 4; ++j)
                    s[i][j] = fmaf(aa[i], bb[j], s[i][j]);
        }

#pragma unroll
        for (int i = 0; i < 4; ++i) {
            float4 mv = *(const float4*)(mask + (size_t)(qr0 + i) * kS + kb + (tx << 2));
            float mk[4] = {mv.x, mv.y, mv.z, mv.w};
#pragma unroll
            for (int j = 0; j < 4; ++j) {
                float p = __expf(fmaf(s[i][j], 0.125f, mk[j]) - mi[i]) * il[i];
                Ps[(tx << 2) + j][(ty << 2) + i] = p;   // transposed [k][q]
            }
        }
        __syncthreads();  // scores done (KVs as K no longer needed), Ps ready
        load_tile_N(KVs, g_v + ((size_t)(b * kS + kb)) * kE + h * kHD, tid);
        __syncthreads();

#pragma unroll
        for (int kk = 0; kk < 64; ++kk) {
            float4 p4 = *(const float4*)&Ps[kk][ty << 2];
            float4 v4 = *(const float4*)&KVs[kk][tx << 2];
            float pp[4] = {p4.x, p4.y, p4.z, p4.w};
            float vv[4] = {v4.x, v4.y, v4.z, v4.w};
#pragma unroll
            for (int i = 0; i < 4; ++i)
#pragma unroll
                for (int j = 0; j < 4; ++j)
                    cacc[i][j] = fmaf(pp[i], vv[j], cacc[i][j]);
        }
    }

#pragma unroll
    for (int i = 0; i < 4; ++i) {
        float4 o = {cacc[i][0], cacc[i][1], cacc[i][2], cacc[i][3]};
        *(float4*)(g_ctx + (size_t)(b * kS + qr0 + i) * kE + h * kHD + (tx << 2)) = o;
    }
}

// ---------------------------------------------------------------------------
// K5: output projection o = ctx @ Wo[m], modality-selected rows -> g_o
// ---------------------------------------------------------------------------
__global__ __launch_bounds__(256) void k_oproj(const float* __restrict__ Wo,
                                               const int* __restrict__ mod_ids)
{
    const int m = blockIdx.z;
    const float* W = Wo + (size_t)m * kE * kD;

    const int tid  = threadIdx.x;
    const int ty   = tid >> 4, tx = tid & 15;
    const int rows = blockIdx.y * 64;
    const int cols = blockIdx.x * 64;

    __shared__ float As[16][64];
    __shared__ float Bs[16][64];

    float acc[4][4] = {};

    const int ar = tid >> 2;
    const int ak = (tid & 3) << 2;
    const int bk = tid >> 4;
    const int bc = (tid & 15) << 2;

    const float* aptr = g_ctx + (size_t)(rows + ar) * kE + ak;
    const float* bptr = W + (size_t)bk * kD + cols + bc;

    for (int k0 = 0; k0 < kE; k0 += 16) {
        float4 av = *(const float4*)(aptr + k0);
        float4 bv = *(const float4*)(bptr + (size_t)k0 * kD);
        __syncthreads();
        As[ak + 0][ar] = av.x;
        As[ak + 1][ar] = av.y;
        As[ak + 2][ar] = av.z;
        As[ak + 3][ar] = av.w;
        *(float4*)&Bs[bk][bc] = bv;
        __syncthreads();
#pragma unroll
        for (int kk = 0; kk < 16; ++kk) {
            float4 a4 = *(const float4*)&As[kk][ty << 2];
            float4 b4 = *(const float4*)&Bs[kk][tx << 2];
            float aa[4] = {a4.x, a4.y, a4.z, a4.w};
            float bb[4] = {b4.x, b4.y, b4.z, b4.w};
#pragma unroll
            for (int i = 0; i < 4; ++i)
#pragma unroll
                for (int j = 0; j < 4; ++j)
                    acc[i][j] = fmaf(aa[i], bb[j], acc[i][j]);
        }
    }

#pragma unroll
    for (int i = 0; i < 4; ++i) {
        int rg = rows + (ty << 2) + i;
        if (mod_ids[rg] == m) {
            float4 o = {acc[i][0], acc[i][1], acc[i][2], acc[i][3]};
            *(float4*)(g_o + (size_t)rg * kD + cols + (tx << 2)) = o;
        }
    }
}

// ---------------------------------------------------------------------------
// K6: full-row RMSNorm over D with modality-selected weight -> final out
// grid = NR blocks, 256 threads (each thread handles exactly one float4)
// ---------------------------------------------------------------------------
__global__ __launch_bounds__(256) void k_rmsout(const int* __restrict__ mod_ids,
                                                const float* __restrict__ anw,
                                                float* __restrict__ out)
{
    const int rg = blockIdx.x;
    const int tid = threadIdx.x;
    const int mid = mod_ids[rg];
    const float* src = g_o + (size_t)rg * kD;

    float4 v = *(const float4*)(src + tid * 4);
    float ss = v.x * v.x + v.y * v.y + v.z * v.z + v.w * v.w;
#pragma unroll
    for (int off = 16; off > 0; off >>= 1)
        ss += __shfl_xor_sync(0xffffffffu, ss, off);

    __shared__ float red[8];
    __shared__ float scale_sh;
    if ((tid & 31) == 0) red[tid >> 5] = ss;
    __syncthreads();
    if (tid == 0) {
        float t = 0.0f;
#pragma unroll
        for (int w = 0; w < 8; ++w) t += red[w];
        scale_sh = rsqrtf(t * (1.0f / kD) + kEps);
    }
    __syncthreads();
    float sc = scale_sh;

    const float* w = anw + (size_t)mid * kD;
    float4 w4 = *(const float4*)(w + tid * 4);
    float4 o;
    o.x = v.x * sc * w4.x;
    o.y = v.y * sc * w4.y;
    o.z = v.z * sc * w4.z;
    o.w = v.w * sc * w4.w;
    *(float4*)(out + (size_t)rg * kD + tid * 4) = o;
}

// ---------------------------------------------------------------------------
extern "C" void kernel_launch(void* const* d_in, const int* in_sizes, int n_in,
                              void* d_out, int out_size)
{
    const float* x         = (const float*)d_in[0];
    const float* attn_mask = (const float*)d_in[1];
    const int*   mod_ids   = (const int*)d_in[2];
    const float* Wq        = (const float*)d_in[3];
    const float* Wk        = (const float*)d_in[4];
    const float* Wv        = (const float*)d_in[5];
    const float* Wo        = (const float*)d_in[6];
    const float* qn_w      = (const float*)d_in[7];
    const float* kn_w      = (const float*)d_in[8];
    const float* anw       = (const float*)d_in[9];

    float* out = (float*)d_out;                     // [B,S,D]
    float* aw  = out + (size_t)kNR * kD;            // [B,S,S]

    // k_ctx uses 52224 B dynamic smem (> 48KB static limit)
    cudaFuncSetAttribute(k_ctx, cudaFuncAttributeMaxDynamicSharedMemorySize,
                         3 * 64 * 68 * 4);

    dim3 blk(256);
    k_qkv  <<<dim3(kE / 64, kNR / 64, 6), blk>>>(x, Wq, Wk, Wv, mod_ids, qn_w, kn_w);
    k_stats<<<dim3(kS / 64, kB * kH), blk>>>(attn_mask);
    k_attnw<<<dim3(kS / 64, kS / 64, kB), blk>>>(attn_mask, aw);
    k_ctx  <<<dim3(kS / 64, kB * kH), blk, 3 * 64 * 68 * 4>>>(attn_mask);
    k_oproj<<<dim3(kD / 64, kNR / 64, kM), blk>>>(Wo, mod_ids);
    k_rmsout<<<kNR, blk>>>(mod_ids, anw, out);
}

// round 2
// speedup vs baseline: 1.3587x; 1.3587x over previous
#include <cuda_runtime.h>

// ---------------------------------------------------------------------------
// SimpleModalityUntiedAttention: B=2 S=2048 D=1024 H=16 HD=64 M=2 E=1024
// Round 2: 128-wide tiles, 8x8 / 8x4 microtiles (64 FMA per 4 LDS.128),
// k_stats fused into flash-ctx kernel (online softmax, emits m,l).
// ---------------------------------------------------------------------------

namespace {
constexpr int kB  = 2;
constexpr int kS  = 2048;
constexpr int kD  = 1024;
constexpr int kH  = 16;
constexpr int kHD = 64;
constexpr int kM  = 2;
constexpr int kE  = 1024;
constexpr int kNR = kB * kS;
constexpr float kEps   = 1e-5f;
constexpr float kScale = 0.125f;   // 1/sqrt(64)
}

__device__ float g_q[kNR * kE];
__device__ float g_k[kNR * kE];
__device__ float g_v[kNR * kE];
__device__ float g_ctx[kNR * kE];
__device__ float g_o[kNR * kD];
__device__ float g_ml[kB * kH * kS * 2];   // (max, sumexp) per (b,h,q)

// ---------------------------------------------------------------------------
// K1: QKV projection, 128x128x16 tiles, 8x8 microtile, fused per-head RMSNorm
// grid.z = m*3 + which (0=q,1=k,2=v)
// ---------------------------------------------------------------------------
__global__ __launch_bounds__(256) void k_qkv(
    const float* __restrict__ x,
    const float* __restrict__ Wq, const float* __restrict__ Wk,
    const float* __restrict__ Wv,
    const int* __restrict__ mod_ids,
    const float* __restrict__ qn_w, const float* __restrict__ kn_w)
{
    const int z = blockIdx.z;
    const int m = z / 3;
    const int which = z % 3;
    const float* W = ((which == 0) ? Wq : (which == 1) ? Wk : Wv) + (size_t)m * kD * kE;
    float* Cout = (which == 0) ? g_q : (which == 1) ? g_k : g_v;

    const int tid = threadIdx.x;
    const int ty = tid >> 4, tx = tid & 15;
    const int rows = blockIdx.y * 128;
    const int cols = blockIdx.x * 128;

    __shared__ float As[16][132];   // [k][row], transposed
    __shared__ float Bs[16][132];   // [k][col]

    float acc[8][8] = {};

    const int ar = tid >> 2, ak = (tid & 3) << 2;
    const int bk = tid >> 5, bc = (tid & 31) << 2;

    const float* ap0 = x + (size_t)(rows + ar) * kD + ak;
    const float* ap1 = ap0 + (size_t)64 * kD;
    const float* bp0 = W + (size_t)bk * kE + cols + bc;
    const float* bp1 = bp0 + (size_t)8 * kE;

    for (int k0 = 0; k0 < kD; k0 += 16) {
        float4 av0 = *(const float4*)(ap0 + k0);
        float4 av1 = *(const float4*)(ap1 + k0);
        float4 bv0 = *(const float4*)(bp0 + (size_t)k0 * kE);
        float4 bv1 = *(const float4*)(bp1 + (size_t)k0 * kE);
        __syncthreads();
        As[ak + 0][ar] = av0.x; As[ak + 1][ar] = av0.y;
        As[ak + 2][ar] = av0.z; As[ak + 3][ar] = av0.w;
        As[ak + 0][ar + 64] = av1.x; As[ak + 1][ar + 64] = av1.y;
        As[ak + 2][ar + 64] = av1.z; As[ak + 3][ar + 64] = av1.w;
        *(float4*)&Bs[bk][bc]     = bv0;
        *(float4*)&Bs[bk + 8][bc] = bv1;
        __syncthreads();
#pragma unroll 8
        for (int kk = 0; kk < 16; ++kk) {
            float4 a0 = *(const float4*)&As[kk][ty << 2];
            float4 a1 = *(const float4*)&As[kk][(ty << 2) + 64];
            float4 b0 = *(const float4*)&Bs[kk][tx << 2];
            float4 b1 = *(const float4*)&Bs[kk][(tx << 2) + 64];
            float aa[8] = {a0.x, a0.y, a0.z, a0.w, a1.x, a1.y, a1.z, a1.w};
            float bb[8] = {b0.x, b0.y, b0.z, b0.w, b1.x, b1.y, b1.z, b1.w};
#pragma unroll
            for (int i = 0; i < 8; ++i)
#pragma unroll
                for (int j = 0; j < 8; ++j)
                    acc[i][j] = fmaf(aa[i], bb[j], acc[i][j]);
        }
    }

    int rown[8], mid[8];
#pragma unroll
    for (int i = 0; i < 8; ++i) {
        rown[i] = rows + (ty << 2) + (i & 3) + ((i >> 2) << 6);
        mid[i] = mod_ids[rown[i]];
    }

    if (which < 2) {
        const float* wn = ((which == 0) ? qn_w : kn_w) + m * kHD;
        float w4[4];
#pragma unroll
        for (int j = 0; j < 4; ++j) w4[j] = wn[(tx << 2) + j];
#pragma unroll
        for (int i = 0; i < 8; ++i) {
            float ss0 = acc[i][0] * acc[i][0] + acc[i][1] * acc[i][1] +
                        acc[i][2] * acc[i][2] + acc[i][3] * acc[i][3];
            float ss1 = acc[i][4] * acc[i][4] + acc[i][5] * acc[i][5] +
                        acc[i][6] * acc[i][6] + acc[i][7] * acc[i][7];
#pragma unroll
            for (int off = 1; off < 16; off <<= 1) {
                ss0 += __shfl_xor_sync(0xffffffffu, ss0, off);
                ss1 += __shfl_xor_sync(0xffffffffu, ss1, off);
            }
            float sc0 = rsqrtf(ss0 * (1.0f / 64.0f) + kEps);
            float sc1 = rsqrtf(ss1 * (1.0f / 64.0f) + kEps);
            if (mid[i] == m) {
                float4 o0 = {acc[i][0] * sc0 * w4[0], acc[i][1] * sc0 * w4[1],
                             acc[i][2] * sc0 * w4[2], acc[i][3] * sc0 * w4[3]};
                float4 o1 = {acc[i][4] * sc1 * w4[0], acc[i][5] * sc1 * w4[1],
                             acc[i][6] * sc1 * w4[2], acc[i][7] * sc1 * w4[3]};
                float* dst = Cout + (size_t)rown[i] * kE + cols + (tx << 2);
                *(float4*)dst = o0;
                *(float4*)(dst + 64) = o1;
            }
        }
    } else {
#pragma unroll
        for (int i = 0; i < 8; ++i) {
            if (mid[i] == m) {
                float4 o0 = {acc[i][0], acc[i][1], acc[i][2], acc[i][3]};
                float4 o1 = {acc[i][4], acc[i][5], acc[i][6], acc[i][7]};
                float* dst = Cout + (size_t)rown[i] * kE + cols + (tx << 2);
                *(float4*)dst = o0;
                *(float4*)(dst + 64) = o1;
            }
        }
    }
}

// ---------------------------------------------------------------------------
// K2: flash attention (online softmax), q-tile=128, k-tile=64.
// Computes ctx = softmax(QK^T/8 + mask) V, and writes (m, l) stats to g_ml.
// grid = (S/128, B*H), block 256, dyn smem 84992 B
// ---------------------------------------------------------------------------
__global__ __launch_bounds__(256) void k_flash(const float* __restrict__ mask)
{
    extern __shared__ float sh[];
    float (*Qs)[132] = (float(*)[132])sh;                       // [d=64][q=128]
    float (*Ks)[68]  = (float(*)[68])(sh + 64 * 132);           // K: [d][k] / V: [k][d]
    float (*Ps)[132] = (float(*)[132])(sh + 64 * 132 + 64 * 68);// [k=64][q=128]

    const int bh = blockIdx.y;
    const int b = bh >> 4, h = bh & 15;
    const int qbase = blockIdx.x * 128;
    const int tid = threadIdx.x;
    const int ty = tid >> 4, tx = tid & 15;

    int qloc[8];
#pragma unroll
    for (int i = 0; i < 8; ++i) qloc[i] = (ty << 2) + (i & 3) + ((i >> 2) << 6);

    // load Q tile transposed [d][q]
    {
        const float* qsrc = g_q + ((size_t)(b * kS + qbase)) * kE + h * kHD;
#pragma unroll
        for (int r = 0; r < 8; ++r) {
            int idx = tid + r * 256;
            int q = idx >> 4, d4 = (idx & 15) << 2;
            float4 v = *(const float4*)(qsrc + (size_t)q * kE + d4);
            Qs[d4 + 0][q] = v.x; Qs[d4 + 1][q] = v.y;
            Qs[d4 + 2][q] = v.z; Qs[d4 + 3][q] = v.w;
        }
    }

    float mr[8], lr[8], acc[8][4] = {};
#pragma unroll
    for (int i = 0; i < 8; ++i) { mr[i] = -3e38f; lr[i] = 0.0f; }

    for (int kb = 0; kb < kS; kb += 64) {
        __syncthreads();   // prev iter done reading Ks(V), Ps
        {
            const float* ksrc = g_k + ((size_t)(b * kS + kb)) * kE + h * kHD;
#pragma unroll
            for (int r = 0; r < 4; ++r) {
                int idx = tid + r * 256;
                int kk = idx >> 4, d4 = (idx & 15) << 2;
                float4 v = *(const float4*)(ksrc + (size_t)kk * kE + d4);
                Ks[d4 + 0][kk] = v.x; Ks[d4 + 1][kk] = v.y;
                Ks[d4 + 2][kk] = v.z; Ks[d4 + 3][kk] = v.w;
            }
        }
        __syncthreads();

        float s[8][4] = {};
#pragma unroll 8
        for (int d = 0; d < 64; ++d) {
            float4 a0 = *(const float4*)&Qs[d][ty << 2];
            float4 a1 = *(const float4*)&Qs[d][(ty << 2) + 64];
            float4 bv = *(const float4*)&Ks[d][tx << 2];
            float aa[8] = {a0.x, a0.y, a0.z, a0.w, a1.x, a1.y, a1.z, a1.w};
            float bb[4] = {bv.x, bv.y, bv.z, bv.w};
#pragma unroll
            for (int i = 0; i < 8; ++i)
#pragma unroll
                for (int j = 0; j < 4; ++j)
                    s[i][j] = fmaf(aa[i], bb[j], s[i][j]);
        }

        // online softmax update; s[][] is overwritten with p = exp(sv - m)
#pragma unroll
        for (int i = 0; i < 8; ++i) {
            float4 mv = *(const float4*)(mask + (size_t)(qbase + qloc[i]) * kS + kb + (tx << 2));
            float sv0 = fmaf(s[i][0], kScale, mv.x);
            float sv1 = fmaf(s[i][1], kScale, mv.y);
            float sv2 = fmaf(s[i][2], kScale, mv.z);
            float sv3 = fmaf(s[i][3], kScale, mv.w);
            float tm = fmaxf(fmaxf(sv0, sv1), fmaxf(sv2, sv3));
#pragma unroll
            for (int off = 1; off < 16; off <<= 1)
                tm = fmaxf(tm, __shfl_xor_sync(0xffffffffu, tm, off));
            float nm = fmaxf(mr[i], tm);
            float corr = __expf(mr[i] - nm);
            s[i][0] = __expf(sv0 - nm); s[i][1] = __expf(sv1 - nm);
            s[i][2] = __expf(sv2 - nm); s[i][3] = __expf(sv3 - nm);
            float ps = s[i][0] + s[i][1] + s[i][2] + s[i][3];
#pragma unroll
            for (int off = 1; off < 16; off <<= 1)
                ps += __shfl_xor_sync(0xffffffffu, ps, off);
            lr[i] = lr[i] * corr + ps;
            mr[i] = nm;
#pragma unroll
            for (int c = 0; c < 4; ++c) acc[i][c] *= corr;
        }

        // write P transposed [k][q] with float4 along q
#pragma unroll
        for (int j = 0; j < 4; ++j) {
            float4 p0 = {s[0][j], s[1][j], s[2][j], s[3][j]};
            float4 p1 = {s[4][j], s[5][j], s[6][j], s[7][j]};
            *(float4*)&Ps[(tx << 2) + j][ty << 2] = p0;
            *(float4*)&Ps[(tx << 2) + j][(ty << 2) + 64] = p1;
        }
        __syncthreads();   // all done reading Ks(K); Ps complete

        {
            const float* vsrc = g_v + ((size_t)(b * kS + kb)) * kE + h * kHD;
#pragma unroll
            for (int r = 0; r < 4; ++r) {
                int idx = tid + r * 256;
                int kk = idx >> 4, d4 = (idx & 15) << 2;
                *(float4*)&Ks[kk][d4] = *(const float4*)(vsrc + (size_t)kk * kE + d4);
            }
        }
        __syncthreads();

#pragma unroll 8
        for (int kk = 0; kk < 64; ++kk) {
            float4 p0 = *(const float4*)&Ps[kk][ty << 2];
            float4 p1 = *(const float4*)&Ps[kk][(ty << 2) + 64];
            float4 vv = *(const float4*)&Ks[kk][tx << 2];
            float pp[8] = {p0.x, p0.y, p0.z, p0.w, p1.x, p1.y, p1.z, p1.w};
            float vb[4] = {vv.x, vv.y, vv.z, vv.w};
#pragma unroll
            for (int i = 0; i < 8; ++i)
#pragma unroll
                for (int c = 0; c < 4; ++c)
                    acc[i][c] = fmaf(pp[i], vb[c], acc[i][c]);
        }
    }

#pragma unroll
    for (int i = 0; i < 8; ++i) {
        float il = 1.0f / lr[i];
        float4 o = {acc[i][0] * il, acc[i][1] * il, acc[i][2] * il, acc[i][3] * il};
        *(float4*)(g_ctx + (size_t)(b * kS + qbase + qloc[i]) * kE + h * kHD + (tx << 2)) = o;
    }
    if (tx == 0) {
#pragma unroll
        for (int i = 0; i < 8; ++i) {
            size_t idx = ((size_t)bh * kS + qbase + qloc[i]) * 2;
            g_ml[idx]     = mr[i];
            g_ml[idx + 1] = lr[i];
        }
    }
}

// ---------------------------------------------------------------------------
// K3: attn_weights = mean over heads of P. Block owns (b, q-tile 128, k-tile 64),
// loops heads, mask tile cached in smem. grid = (S/64, S/128, B), dyn smem 86016B
// ---------------------------------------------------------------------------
__global__ __launch_bounds__(256) void k_attnw(const float* __restrict__ mask,
                                               float* __restrict__ aw_out)
{
    extern __shared__ float sh[];
    float (*Qs)[132] = (float(*)[132])sh;                       // [d=64][q=128]
    float (*Ks)[68]  = (float(*)[68])(sh + 64 * 132);           // [d=64][k=64]
    float (*Ms)[68]  = (float(*)[68])(sh + 64 * 132 + 64 * 68); // [q=128][k=64]

    const int b = blockIdx.z;
    const int qbase = blockIdx.y * 128;
    const int kbase = blockIdx.x * 64;
    const int tid = threadIdx.x;
    const int ty = tid >> 4, tx = tid & 15;

    int qloc[8];
#pragma unroll
    for (int i = 0; i < 8; ++i) qloc[i] = (ty << 2) + (i & 3) + ((i >> 2) << 6);

    // cache mask tile
#pragma unroll
    for (int r = 0; r < 8; ++r) {
        int idx = tid + r * 256;
        int q = idx >> 4, k4 = (idx & 15) << 2;
        *(float4*)&Ms[q][k4] = *(const float4*)(mask + (size_t)(qbase + q) * kS + kbase + k4);
    }

    float aw[8][4] = {};

    for (int h = 0; h < kH; ++h) {
        __syncthreads();
        {
            const float* qsrc = g_q + ((size_t)(b * kS + qbase)) * kE + h * kHD;
#pragma unroll
            for (int r = 0; r < 8; ++r) {
                int idx = tid + r * 256;
                int q = idx >> 4, d4 = (idx & 15) << 2;
                float4 v = *(const float4*)(qsrc + (size_t)q * kE + d4);
                Qs[d4 + 0][q] = v.x; Qs[d4 + 1][q] = v.y;
                Qs[d4 + 2][q] = v.z; Qs[d4 + 3][q] = v.w;
            }
            const float* ksrc = g_k + ((size_t)(b * kS + kbase)) * kE + h * kHD;
#pragma unroll
            for (int r = 0; r < 4; ++r) {
                int idx = tid + r * 256;
                int kk = idx >> 4, d4 = (idx & 15) << 2;
                float4 v = *(const float4*)(ksrc + (size_t)kk * kE + d4);
                Ks[d4 + 0][kk] = v.x; Ks[d4 + 1][kk] = v.y;
                Ks[d4 + 2][kk] = v.z; Ks[d4 + 3][kk] = v.w;
            }
        }
        __syncthreads();

        float s[8][4] = {};
#pragma unroll 8
        for (int d = 0; d < 64; ++d) {
            float4 a0 = *(const float4*)&Qs[d][ty << 2];
            float4 a1 = *(const float4*)&Qs[d][(ty << 2) + 64];
            float4 bv = *(const float4*)&Ks[d][tx << 2];
            float aa[8] = {a0.x, a0.y, a0.z, a0.w, a1.x, a1.y, a1.z, a1.w};
            float bb[4] = {bv.x, bv.y, bv.z, bv.w};
#pragma unroll
            for (int i = 0; i < 8; ++i)
#pragma unroll
                for (int j = 0; j < 4; ++j)
                    s[i][j] = fmaf(aa[i], bb[j], s[i][j]);
        }

#pragma unroll
        for (int i = 0; i < 8; ++i) {
            float2 ml = *(const float2*)&g_ml[((size_t)(b * kH + h) * kS + qbase + qloc[i]) * 2];
            float mi = ml.x;
            float il = 1.0f / ml.y;
            float4 mv = *(const float4*)&Ms[qloc[i]][tx << 2];
            aw[i][0] += __expf(fmaf(s[i][0], kScale, mv.x) - mi) * il;
            aw[i][1] += __expf(fmaf(s[i][1], kScale, mv.y) - mi) * il;
            aw[i][2] += __expf(fmaf(s[i][2], kScale, mv.z) - mi) * il;
            aw[i][3] += __expf(fmaf(s[i][3], kScale, mv.w) - mi) * il;
        }
    }

#pragma unroll
    for (int i = 0; i < 8; ++i) {
        float4 o = {aw[i][0] * (1.0f / kH), aw[i][1] * (1.0f / kH),
                    aw[i][2] * (1.0f / kH), aw[i][3] * (1.0f / kH)};
        *(float4*)(aw_out + (size_t)b * kS * kS +
                   (size_t)(qbase + qloc[i]) * kS + kbase + (tx << 2)) = o;
    }
}

// ---------------------------------------------------------------------------
// K4: output projection, 128x128x16 tiles, 8x8 microtile, modality-selected
// ---------------------------------------------------------------------------
__global__ __launch_bounds__(256) void k_oproj(const float* __restrict__ Wo,
                                               const int* __restrict__ mod_ids)
{
    const int m = blockIdx.z;
    const float* W = Wo + (size_t)m * kE * kD;

    const int tid = threadIdx.x;
    const int ty = tid >> 4, tx = tid & 15;
    const int rows = blockIdx.y * 128;
    const int cols = blockIdx.x * 128;

    __shared__ float As[16][132];
    __shared__ float Bs[16][132];

    float acc[8][8] = {};

    const int ar = tid >> 2, ak = (tid & 3) << 2;
    const int bk = tid >> 5, bc = (tid & 31) << 2;

    const float* ap0 = g_ctx + (size_t)(rows + ar) * kE + ak;
    const float* ap1 = ap0 + (size_t)64 * kE;
    const float* bp0 = W + (size_t)bk * kD + cols + bc;
    const float* bp1 = bp0 + (size_t)8 * kD;

    for (int k0 = 0; k0 < kE; k0 += 16) {
        float4 av0 = *(const float4*)(ap0 + k0);
        float4 av1 = *(const float4*)(ap1 + k0);
        float4 bv0 = *(const float4*)(bp0 + (size_t)k0 * kD);
        float4 bv1 = *(const float4*)(bp1 + (size_t)k0 * kD);
        __syncthreads();
        As[ak + 0][ar] = av0.x; As[ak + 1][ar] = av0.y;
        As[ak + 2][ar] = av0.z; As[ak + 3][ar] = av0.w;
        As[ak + 0][ar + 64] = av1.x; As[ak + 1][ar + 64] = av1.y;
        As[ak + 2][ar + 64] = av1.z; As[ak + 3][ar + 64] = av1.w;
        *(float4*)&Bs[bk][bc]     = bv0;
        *(float4*)&Bs[bk + 8][bc] = bv1;
        __syncthreads();
#pragma unroll 8
        for (int kk = 0; kk < 16; ++kk) {
            float4 a0 = *(const float4*)&As[kk][ty << 2];
            float4 a1 = *(const float4*)&As[kk][(ty << 2) + 64];
            float4 b0 = *(const float4*)&Bs[kk][tx << 2];
            float4 b1 = *(const float4*)&Bs[kk][(tx << 2) + 64];
            float aa[8] = {a0.x, a0.y, a0.z, a0.w, a1.x, a1.y, a1.z, a1.w};
            float bb[8] = {b0.x, b0.y, b0.z, b0.w, b1.x, b1.y, b1.z, b1.w};
#pragma unroll
            for (int i = 0; i < 8; ++i)
#pragma unroll
                for (int j = 0; j < 8; ++j)
                    acc[i][j] = fmaf(aa[i], bb[j], acc[i][j]);
        }
    }

#pragma unroll
    for (int i = 0; i < 8; ++i) {
        int rg = rows + (ty << 2) + (i & 3) + ((i >> 2) << 6);
        if (mod_ids[rg] == m) {
            float4 o0 = {acc[i][0], acc[i][1], acc[i][2], acc[i][3]};
            float4 o1 = {acc[i][4], acc[i][5], acc[i][6], acc[i][7]};
            float* dst = g_o + (size_t)rg * kD + cols + (tx << 2);
            *(float4*)dst = o0;
            *(float4*)(dst + 64) = o1;
        }
    }
}

// ---------------------------------------------------------------------------
// K5: full-row RMSNorm over D with modality-selected weight -> final out
// ---------------------------------------------------------------------------
__global__ __launch_bounds__(256) void k_rmsout(const int* __restrict__ mod_ids,
                                                const float* __restrict__ anw,
                                                float* __restrict__ out)
{
    const int rg = blockIdx.x;
    const int tid = threadIdx.x;
    const int mid = mod_ids[rg];
    const float* src = g_o + (size_t)rg * kD;

    float4 v = *(const float4*)(src + tid * 4);
    float ss = v.x * v.x + v.y * v.y + v.z * v.z + v.w * v.w;
#pragma unroll
    for (int off = 16; off > 0; off >>= 1)
        ss += __shfl_xor_sync(0xffffffffu, ss, off);

    __shared__ float red[8];
    __shared__ float scale_sh;
    if ((tid & 31) == 0) red[tid >> 5] = ss;
    __syncthreads();
    if (tid == 0) {
        float t = 0.0f;
#pragma unroll
        for (int w = 0; w < 8; ++w) t += red[w];
        scale_sh = rsqrtf(t * (1.0f / kD) + kEps);
    }
    __syncthreads();
    float sc = scale_sh;

    const float* w = anw + (size_t)mid * kD;
    float4 w4 = *(const float4*)(w + tid * 4);
    float4 o = {v.x * sc * w4.x, v.y * sc * w4.y, v.z * sc * w4.z, v.w * sc * w4.w};
    *(float4*)(out + (size_t)rg * kD + tid * 4) = o;
}

// ---------------------------------------------------------------------------
extern "C" void kernel_launch(void* const* d_in, const int* in_sizes, int n_in,
                              void* d_out, int out_size)
{
    const float* x         = (const float*)d_in[0];
    const float* attn_mask = (const float*)d_in[1];
    const int*   mod_ids   = (const int*)d_in[2];
    const float* Wq        = (const float*)d_in[3];
    const float* Wk        = (const float*)d_in[4];
    const float* Wv        = (const float*)d_in[5];
    const float* Wo        = (const float*)d_in[6];
    const float* qn_w      = (const float*)d_in[7];
    const float* kn_w      = (const float*)d_in[8];
    const float* anw       = (const float*)d_in[9];

    float* out = (float*)d_out;             // [B,S,D]
    float* aw  = out + (size_t)kNR * kD;    // [B,S,S]

    constexpr int kFlashSmem = (64 * 132 + 64 * 68 + 64 * 132) * 4;   // 84992
    constexpr int kAttnwSmem = (64 * 132 + 64 * 68 + 128 * 68) * 4;   // 86016
    cudaFuncSetAttribute(k_flash, cudaFuncAttributeMaxDynamicSharedMemorySize, kFlashSmem);
    cudaFuncSetAttribute(k_attnw, cudaFuncAttributeMaxDynamicSharedMemorySize, kAttnwSmem);

    dim3 blk(256);
    k_qkv  <<<dim3(kE / 128, kNR / 128, 6), blk>>>(x, Wq, Wk, Wv, mod_ids, qn_w, kn_w);
    k_flash<<<dim3(kS / 128, kB * kH), blk, kFlashSmem>>>(attn_mask);
    k_attnw<<<dim3(kS / 64, kS / 128, kB), blk, kAttnwSmem>>>(attn_mask, aw);
    k_oproj<<<dim3(kD / 128, kNR / 128, kM), blk>>>(Wo, mod_ids);
    k_rmsout<<<kNR, blk>>>(mod_ids, anw, out);
}

// round 3
// speedup vs baseline: 3.3637x; 2.4757x over previous
#include <cuda_runtime.h>
#include <cstdint>

// ---------------------------------------------------------------------------
// SimpleModalityUntiedAttention: B=2 S=2048 D=1024 H=16 HD=64 M=2 E=1024
// Round 3: tf32 mma.sync.m16n8k8 tensor-core path for all GEMM stages.
// fp32 accumulate; inputs rounded to tf32 (cvt.rna) at smem-store time.
// ---------------------------------------------------------------------------

namespace {
constexpr int kB  = 2;
constexpr int kS  = 2048;
constexpr int kD  = 1024;
constexpr int kH  = 16;
constexpr int kHD = 64;
constexpr int kM  = 2;
constexpr int kE  = 1024;
constexpr int kNR = kB * kS;
constexpr float kEps   = 1e-5f;
constexpr float kScale = 0.125f;
}

__device__ float g_q[kNR * kE];
__device__ float g_k[kNR * kE];
__device__ float g_v[kNR * kE];
__device__ float g_ctx[kNR * kE];
__device__ float g_o[kNR * kD];
__device__ float g_ml[kB * kH * kS * 2];

__device__ __forceinline__ float f2tf(float x) {
    uint32_t u;
    asm("cvt.rna.tf32.f32 %0, %1;" : "=r"(u) : "f"(x));
    return __uint_as_float(u);
}
__device__ __forceinline__ uint32_t fu(float x) { return __float_as_uint(x); }

// D(16x8) += A(16x8) * B(8x8), tf32 inputs (as raw f32 regs), f32 accum.
__device__ __forceinline__ void mma_tf32(float* d, const uint32_t* a, const uint32_t* b) {
    asm volatile(
        "mma.sync.aligned.m16n8k8.row.col.f32.tf32.tf32.f32 "
        "{%0,%1,%2,%3}, {%4,%5,%6,%7}, {%8,%9}, {%0,%1,%2,%3};"
        : "+f"(d[0]), "+f"(d[1]), "+f"(d[2]), "+f"(d[3])
        : "r"(a[0]), "r"(a[1]), "r"(a[2]), "r"(a[3]), "r"(b[0]), "r"(b[1]));
}

// Fragment loads. A row-major [r][k] array with stride `st`:
//   a0=(g,t) a1=(g+8,t) a2=(g,t+4) a3=(g+8,t+4); g=lane/4, t=lane%4
// B "natural [n][k]" array (= col-major k x n): b0=(k=t,n=g) b1=(k=t+4,n=g)

// ---------------------------------------------------------------------------
// K1: QKV projection, 128x128 block tile, tf32 mma. Warp tile 32x64 (n0 is
// 64-aligned so each warp's columns span exactly one head -> fused RMSNorm).
// grid.z = m*3 + which (0=q,1=k,2=v)
// ---------------------------------------------------------------------------
__global__ __launch_bounds__(256) void k_qkv(
    const float* __restrict__ x,
    const float* __restrict__ Wq, const float* __restrict__ Wk,
    const float* __restrict__ Wv,
    const int* __restrict__ mod_ids,
    const float* __restrict__ qn_w, const float* __restrict__ kn_w)
{
    const int z = blockIdx.z;
    const int m = z / 3;
    const int which = z % 3;
    const float* W = ((which == 0) ? Wq : (which == 1) ? Wk : Wv) + (size_t)m * kD * kE;
    float* Cout = (which == 0) ? g_q : (which == 1) ? g_k : g_v;

    const int tid = threadIdx.x;
    const int wid = tid >> 5, lane = tid & 31;
    const int lg = lane >> 2, lt = lane & 3;
    const int wm = wid & 3, wn = wid >> 2;        // 4 x 2 warps
    const int rows = blockIdx.y * 128;
    const int cols = blockIdx.x * 128;

    __shared__ float As[128][20];   // [row][k], row-major, pad 20
    __shared__ float Bs[16][136];   // [k][n], pad 136

    float d[2][8][4] = {};

    const int ar0 = tid >> 2, ac0 = (tid & 3) << 2;          // + tid+256 variant
    const int bk0 = tid >> 5, bn0 = (tid & 31) << 2;

    for (int k0 = 0; k0 < kD; k0 += 16) {
        float4 av0 = *(const float4*)(x + (size_t)(rows + ar0) * kD + k0 + ac0);
        float4 av1 = *(const float4*)(x + (size_t)(rows + ar0 + 64) * kD + k0 + ac0);
        float4 bv0 = *(const float4*)(W + (size_t)(k0 + bk0) * kE + cols + bn0);
        float4 bv1 = *(const float4*)(W + (size_t)(k0 + bk0 + 8) * kE + cols + bn0);
        __syncthreads();
        {
            float4 t0 = {f2tf(av0.x), f2tf(av0.y), f2tf(av0.z), f2tf(av0.w)};
            float4 t1 = {f2tf(av1.x), f2tf(av1.y), f2tf(av1.z), f2tf(av1.w)};
            *(float4*)&As[ar0][ac0] = t0;
            *(float4*)&As[ar0 + 64][ac0] = t1;
            float4 u0 = {f2tf(bv0.x), f2tf(bv0.y), f2tf(bv0.z), f2tf(bv0.w)};
            float4 u1 = {f2tf(bv1.x), f2tf(bv1.y), f2tf(bv1.z), f2tf(bv1.w)};
            *(float4*)&Bs[bk0][bn0] = u0;
            *(float4*)&Bs[bk0 + 8][bn0] = u1;
        }
        __syncthreads();
#pragma unroll
        for (int ks = 0; ks < 16; ks += 8) {
            uint32_t a[2][4], b[8][2];
#pragma unroll
            for (int mi = 0; mi < 2; ++mi) {
                int r = wm * 32 + mi * 16 + lg;
                a[mi][0] = fu(As[r][ks + lt]);
                a[mi][1] = fu(As[r + 8][ks + lt]);
                a[mi][2] = fu(As[r][ks + 4 + lt]);
                a[mi][3] = fu(As[r + 8][ks + 4 + lt]);
            }
#pragma unroll
            for (int ni = 0; ni < 8; ++ni) {
                int n = wn * 64 + ni * 8 + lg;
                b[ni][0] = fu(Bs[ks + lt][n]);
                b[ni][1] = fu(Bs[ks + 4 + lt][n]);
            }
#pragma unroll
            for (int mi = 0; mi < 2; ++mi)
#pragma unroll
                for (int ni = 0; ni < 8; ++ni)
                    mma_tf32(d[mi][ni], a[mi], b[ni]);
        }
    }

    // epilogue: per-row (4 rows/thread), per-head RMSNorm for q/k
    const float* wn_ptr = ((which == 0) ? qn_w : kn_w) + m * kHD;
#pragma unroll
    for (int mi = 0; mi < 2; ++mi) {
#pragma unroll
        for (int hh = 0; hh < 2; ++hh) {
            int row = rows + wm * 32 + mi * 16 + hh * 8 + lg;
            int c0 = hh * 2, c1 = hh * 2 + 1;
            bool sel = (mod_ids[row] == m);
            if (which < 2) {
                float ss = 0.0f;
#pragma unroll
                for (int ni = 0; ni < 8; ++ni)
                    ss += d[mi][ni][c0] * d[mi][ni][c0] + d[mi][ni][c1] * d[mi][ni][c1];
                ss += __shfl_xor_sync(0xffffffffu, ss, 1);
                ss += __shfl_xor_sync(0xffffffffu, ss, 2);
                float sc = rsqrtf(ss * (1.0f / 64.0f) + kEps);
                if (sel) {
#pragma unroll
                    for (int ni = 0; ni < 8; ++ni) {
                        int cl = ni * 8 + lt * 2;      // head-local col
                        float2 o = {d[mi][ni][c0] * sc * wn_ptr[cl],
                                    d[mi][ni][c1] * sc * wn_ptr[cl + 1]};
                        *(float2*)(Cout + (size_t)row * kE + cols + wn * 64 + cl) = o;
                    }
                }
            } else if (sel) {
#pragma unroll
                for (int ni = 0; ni < 8; ++ni) {
                    int cl = ni * 8 + lt * 2;
                    float2 o = {d[mi][ni][c0], d[mi][ni][c1]};
                    *(float2*)(Cout + (size_t)row * kE + cols + wn * 64 + cl) = o;
                }
            }
        }
    }
}

// ---------------------------------------------------------------------------
// K2: flash attention, q-tile 128 (16 rows/warp), k-tile 64, tf32 mma for
// both QK^T and PV. Emits (m,l) to g_ml. grid = (S/128, B*H)
// ---------------------------------------------------------------------------
__global__ __launch_bounds__(256) void k_flash(const float* __restrict__ mask)
{
    extern __shared__ float sh[];
    float (*Qs)[68] = (float(*)[68])sh;                        // [q][d]
    float (*Ks)[68] = (float(*)[68])(sh + 128 * 68);           // [kc][d]
    float (*Vs)[68] = (float(*)[68])(sh + 192 * 68);           // [d][kc] (V^T)
    float (*Ps)[68] = (float(*)[68])(sh + 256 * 68);           // [q][kc]

    const int bh = blockIdx.y;
    const int b = bh >> 4, h = bh & 15;
    const int qbase = blockIdx.x * 128;
    const int tid = threadIdx.x;
    const int wid = tid >> 5, lane = tid & 31;
    const int lg = lane >> 2, lt = lane & 3;
    const int r0 = wid * 16;

    // Q tile (cvt to tf32)
    {
        const float* qsrc = g_q + ((size_t)(b * kS + qbase)) * kE + h * kHD;
#pragma unroll
        for (int rr = 0; rr < 8; ++rr) {
            int idx = tid + rr * 256;
            int q = idx >> 4, d4 = (idx & 15) << 2;
            float4 v = *(const float4*)(qsrc + (size_t)q * kE + d4);
            float4 t = {f2tf(v.x), f2tf(v.y), f2tf(v.z), f2tf(v.w)};
            *(float4*)&Qs[q][d4] = t;
        }
    }

    float oacc[8][4] = {};
    float mr[2] = {-3e38f, -3e38f}, lr[2] = {0.0f, 0.0f};
    const int qrow0 = qbase + r0 + lg;
    const int qrow1 = qrow0 + 8;

    for (int kb = 0; kb < kS; kb += 64) {
        __syncthreads();
        {
            const float* ksrc = g_k + ((size_t)(b * kS + kb)) * kE + h * kHD;
            const float* vsrc = g_v + ((size_t)(b * kS + kb)) * kE + h * kHD;
#pragma unroll
            for (int rr = 0; rr < 4; ++rr) {
                int idx = tid + rr * 256;
                int kc = idx >> 4, d4 = (idx & 15) << 2;
                float4 v = *(const float4*)(ksrc + (size_t)kc * kE + d4);
                float4 t = {f2tf(v.x), f2tf(v.y), f2tf(v.z), f2tf(v.w)};
                *(float4*)&Ks[kc][d4] = t;
                float4 w = *(const float4*)(vsrc + (size_t)kc * kE + d4);
                Vs[d4 + 0][kc] = f2tf(w.x);
                Vs[d4 + 1][kc] = f2tf(w.y);
                Vs[d4 + 2][kc] = f2tf(w.z);
                Vs[d4 + 3][kc] = f2tf(w.w);
            }
        }
        __syncthreads();

        // S = Q K^T
        float s[8][4] = {};
#pragma unroll
        for (int ks = 0; ks < 64; ks += 8) {
            uint32_t a[4];
            a[0] = fu(Qs[r0 + lg][ks + lt]);
            a[1] = fu(Qs[r0 + 8 + lg][ks + lt]);
            a[2] = fu(Qs[r0 + lg][ks + 4 + lt]);
            a[3] = fu(Qs[r0 + 8 + lg][ks + 4 + lt]);
#pragma unroll
            for (int ni = 0; ni < 8; ++ni) {
                uint32_t bfr[2];
                bfr[0] = fu(Ks[ni * 8 + lg][ks + lt]);
                bfr[1] = fu(Ks[ni * 8 + lg][ks + 4 + lt]);
                mma_tf32(s[ni], a, bfr);
            }
        }

        // scale + mask
#pragma unroll
        for (int ni = 0; ni < 8; ++ni) {
            size_t col = (size_t)kb + ni * 8 + lt * 2;
            float2 m0 = *(const float2*)(mask + (size_t)qrow0 * kS + col);
            float2 m1 = *(const float2*)(mask + (size_t)qrow1 * kS + col);
            s[ni][0] = fmaf(s[ni][0], kScale, m0.x);
            s[ni][1] = fmaf(s[ni][1], kScale, m0.y);
            s[ni][2] = fmaf(s[ni][2], kScale, m1.x);
            s[ni][3] = fmaf(s[ni][3], kScale, m1.y);
        }

        // online softmax, both row-groups
#pragma unroll
        for (int rp = 0; rp < 2; ++rp) {
            int i0 = rp * 2, i1 = rp * 2 + 1;
            float tm = -3e38f;
#pragma unroll
            for (int ni = 0; ni < 8; ++ni)
                tm = fmaxf(tm, fmaxf(s[ni][i0], s[ni][i1]));
            tm = fmaxf(tm, __shfl_xor_sync(0xffffffffu, tm, 1));
            tm = fmaxf(tm, __shfl_xor_sync(0xffffffffu, tm, 2));
            float nm = fmaxf(mr[rp], tm);
            float corr = __expf(mr[rp] - nm);
            float ps = 0.0f;
#pragma unroll
            for (int ni = 0; ni < 8; ++ni) {
                s[ni][i0] = __expf(s[ni][i0] - nm);
                s[ni][i1] = __expf(s[ni][i1] - nm);
                ps += s[ni][i0] + s[ni][i1];
            }
            ps += __shfl_xor_sync(0xffffffffu, ps, 1);
            ps += __shfl_xor_sync(0xffffffffu, ps, 2);
            lr[rp] = lr[rp] * corr + ps;
            mr[rp] = nm;
#pragma unroll
            for (int ni = 0; ni < 8; ++ni) {
                oacc[ni][i0] *= corr;
                oacc[ni][i1] *= corr;
            }
        }

        // P to smem (warp-private rows), tf32
#pragma unroll
        for (int ni = 0; ni < 8; ++ni) {
            int cl = ni * 8 + lt * 2;
            float2 p0 = {f2tf(s[ni][0]), f2tf(s[ni][1])};
            float2 p1 = {f2tf(s[ni][2]), f2tf(s[ni][3])};
            *(float2*)&Ps[r0 + lg][cl] = p0;
            *(float2*)&Ps[r0 + 8 + lg][cl] = p1;
        }
        __syncwarp();

        // O += P V
#pragma unroll
        for (int ks = 0; ks < 64; ks += 8) {
            uint32_t a[4];
            a[0] = fu(Ps[r0 + lg][ks + lt]);
            a[1] = fu(Ps[r0 + 8 + lg][ks + lt]);
            a[2] = fu(Ps[r0 + lg][ks + 4 + lt]);
            a[3] = fu(Ps[r0 + 8 + lg][ks + 4 + lt]);
#pragma unroll
            for (int ni = 0; ni < 8; ++ni) {
                uint32_t bfr[2];
                bfr[0] = fu(Vs[ni * 8 + lg][ks + lt]);
                bfr[1] = fu(Vs[ni * 8 + lg][ks + 4 + lt]);
                mma_tf32(oacc[ni], a, bfr);
            }
        }
    }

    float il0 = 1.0f / lr[0], il1 = 1.0f / lr[1];
#pragma unroll
    for (int ni = 0; ni < 8; ++ni) {
        int cl = ni * 8 + lt * 2;
        float2 o0 = {oacc[ni][0] * il0, oacc[ni][1] * il0};
        float2 o1 = {oacc[ni][2] * il1, oacc[ni][3] * il1};
        *(float2*)(g_ctx + (size_t)(b * kS + qrow0) * kE + h * kHD + cl) = o0;
        *(float2*)(g_ctx + (size_t)(b * kS + qrow1) * kE + h * kHD + cl) = o1;
    }
    if (lt == 0) {
        size_t i0 = ((size_t)bh * kS + qrow0) * 2;
        size_t i1 = ((size_t)bh * kS + qrow1) * 2;
        g_ml[i0] = mr[0]; g_ml[i0 + 1] = lr[0];
        g_ml[i1] = mr[1]; g_ml[i1 + 1] = lr[1];
    }
}

// ---------------------------------------------------------------------------
// K3: attn_weights = mean_h softmax. Block = (b, q-tile 128, k-tile 64),
// loops 16 heads with tf32 QK^T, mask + aw kept in regs.
// grid = (S/64, S/128, B)
// ---------------------------------------------------------------------------
__global__ __launch_bounds__(256) void k_attnw(const float* __restrict__ mask,
                                               float* __restrict__ aw_out)
{
    extern __shared__ float sh[];
    float (*Qs)[68] = (float(*)[68])sh;
    float (*Ks)[68] = (float(*)[68])(sh + 128 * 68);

    const int b = blockIdx.z;
    const int qbase = blockIdx.y * 128;
    const int kbase = blockIdx.x * 64;
    const int tid = threadIdx.x;
    const int wid = tid >> 5, lane = tid & 31;
    const int lg = lane >> 2, lt = lane & 3;
    const int r0 = wid * 16;
    const int qrow0 = qbase + r0 + lg;
    const int qrow1 = qrow0 + 8;

    float mk[8][4];
#pragma unroll
    for (int ni = 0; ni < 8; ++ni) {
        size_t col = (size_t)kbase + ni * 8 + lt * 2;
        float2 m0 = *(const float2*)(mask + (size_t)qrow0 * kS + col);
        float2 m1 = *(const float2*)(mask + (size_t)qrow1 * kS + col);
        mk[ni][0] = m0.x; mk[ni][1] = m0.y;
        mk[ni][2] = m1.x; mk[ni][3] = m1.y;
    }

    float aw[8][4] = {};

    for (int h = 0; h < kH; ++h) {
        __syncthreads();
        {
            const float* qsrc = g_q + ((size_t)(b * kS + qbase)) * kE + h * kHD;
#pragma unroll
            for (int rr = 0; rr < 8; ++rr) {
                int idx = tid + rr * 256;
                int q = idx >> 4, d4 = (idx & 15) << 2;
                float4 v = *(const float4*)(qsrc + (size_t)q * kE + d4);
                float4 t = {f2tf(v.x), f2tf(v.y), f2tf(v.z), f2tf(v.w)};
                *(float4*)&Qs[q][d4] = t;
            }
            const float* ksrc = g_k + ((size_t)(b * kS + kbase)) * kE + h * kHD;
#pragma unroll
            for (int rr = 0; rr < 4; ++rr) {
                int idx = tid + rr * 256;
                int kc = idx >> 4, d4 = (idx & 15) << 2;
                float4 v = *(const float4*)(ksrc + (size_t)kc * kE + d4);
                float4 t = {f2tf(v.x), f2tf(v.y), f2tf(v.z), f2tf(v.w)};
                *(float4*)&Ks[kc][d4] = t;
            }
        }
        __syncthreads();

        float s[8][4] = {};
#pragma unroll
        for (int ks = 0; ks < 64; ks += 8) {
            uint32_t a[4];
            a[0] = fu(Qs[r0 + lg][ks + lt]);
            a[1] = fu(Qs[r0 + 8 + lg][ks + lt]);
            a[2] = fu(Qs[r0 + lg][ks + 4 + lt]);
            a[3] = fu(Qs[r0 + 8 + lg][ks + 4 + lt]);
#pragma unroll
            for (int ni = 0; ni < 8; ++ni) {
                uint32_t bfr[2];
                bfr[0] = fu(Ks[ni * 8 + lg][ks + lt]);
                bfr[1] = fu(Ks[ni * 8 + lg][ks + 4 + lt]);
                mma_tf32(s[ni], a, bfr);
            }
        }

        float2 ml0 = *(const float2*)&g_ml[((size_t)(b * kH + h) * kS + qrow0) * 2];
        float2 ml1 = *(const float2*)&g_ml[((size_t)(b * kH + h) * kS + qrow1) * 2];
        float mi0 = ml0.x, il0 = 1.0f / ml0.y;
        float mi1 = ml1.x, il1 = 1.0f / ml1.y;
#pragma unroll
        for (int ni = 0; ni < 8; ++ni) {
            aw[ni][0] += __expf(fmaf(s[ni][0], kScale, mk[ni][0]) - mi0) * il0;
            aw[ni][1] += __expf(fmaf(s[ni][1], kScale, mk[ni][1]) - mi0) * il0;
            aw[ni][2] += __expf(fmaf(s[ni][2], kScale, mk[ni][2]) - mi1) * il1;
            aw[ni][3] += __expf(fmaf(s[ni][3], kScale, mk[ni][3]) - mi1) * il1;
        }
    }

#pragma unroll
    for (int ni = 0; ni < 8; ++ni) {
        int col = kbase + ni * 8 + lt * 2;
        float2 o0 = {aw[ni][0] * (1.0f / kH), aw[ni][1] * (1.0f / kH)};
        float2 o1 = {aw[ni][2] * (1.0f / kH), aw[ni][3] * (1.0f / kH)};
        *(float2*)(aw_out + (size_t)b * kS * kS + (size_t)qrow0 * kS + col) = o0;
        *(float2*)(aw_out + (size_t)b * kS * kS + (size_t)qrow1 * kS + col) = o1;
    }
}

// ---------------------------------------------------------------------------
// K4: output projection, same tf32 GEMM skeleton as k_qkv, modality-gated.
// ---------------------------------------------------------------------------
__global__ __launch_bounds__(256) void k_oproj(const float* __restrict__ Wo,
                                               const int* __restrict__ mod_ids)
{
    const int m = blockIdx.z;
    const float* W = Wo + (size_t)m * kE * kD;

    const int tid = threadIdx.x;
    const int wid = tid >> 5, lane = tid & 31;
    const int lg = lane >> 2, lt = lane & 3;
    const int wm = wid & 3, wn = wid >> 2;
    const int rows = blockIdx.y * 128;
    const int cols = blockIdx.x * 128;

    __shared__ float As[128][20];
    __shared__ float Bs[16][136];

    float d[2][8][4] = {};

    const int ar0 = tid >> 2, ac0 = (tid & 3) << 2;
    const int bk0 = tid >> 5, bn0 = (tid & 31) << 2;

    for (int k0 = 0; k0 < kE; k0 += 16) {
        float4 av0 = *(const float4*)(g_ctx + (size_t)(rows + ar0) * kE + k0 + ac0);
        float4 av1 = *(const float4*)(g_ctx + (size_t)(rows + ar0 + 64) * kE + k0 + ac0);
        float4 bv0 = *(const float4*)(W + (size_t)(k0 + bk0) * kD + cols + bn0);
        float4 bv1 = *(const float4*)(W + (size_t)(k0 + bk0 + 8) * kD + cols + bn0);
        __syncthreads();
        {
            float4 t0 = {f2tf(av0.x), f2tf(av0.y), f2tf(av0.z), f2tf(av0.w)};
            float4 t1 = {f2tf(av1.x), f2tf(av1.y), f2tf(av1.z), f2tf(av1.w)};
            *(float4*)&As[ar0][ac0] = t0;
            *(float4*)&As[ar0 + 64][ac0] = t1;
            float4 u0 = {f2tf(bv0.x), f2tf(bv0.y), f2tf(bv0.z), f2tf(bv0.w)};
            float4 u1 = {f2tf(bv1.x), f2tf(bv1.y), f2tf(bv1.z), f2tf(bv1.w)};
            *(float4*)&Bs[bk0][bn0] = u0;
            *(float4*)&Bs[bk0 + 8][bn0] = u1;
        }
        __syncthreads();
#pragma unroll
        for (int ks = 0; ks < 16; ks += 8) {
            uint32_t a[2][4], b[8][2];
#pragma unroll
            for (int mi = 0; mi < 2; ++mi) {
                int r = wm * 32 + mi * 16 + lg;
                a[mi][0] = fu(As[r][ks + lt]);
                a[mi][1] = fu(As[r + 8][ks + lt]);
                a[mi][2] = fu(As[r][ks + 4 + lt]);
                a[mi][3] = fu(As[r + 8][ks + 4 + lt]);
            }
#pragma unroll
            for (int ni = 0; ni < 8; ++ni) {
                int n = wn * 64 + ni * 8 + lg;
                b[ni][0] = fu(Bs[ks + lt][n]);
                b[ni][1] = fu(Bs[ks + 4 + lt][n]);
            }
#pragma unroll
            for (int mi = 0; mi < 2; ++mi)
#pragma unroll
                for (int ni = 0; ni < 8; ++ni)
                    mma_tf32(d[mi][ni], a[mi], b[ni]);
        }
    }

#pragma unroll
    for (int mi = 0; mi < 2; ++mi) {
#pragma unroll
        for (int hh = 0; hh < 2; ++hh) {
            int row = rows + wm * 32 + mi * 16 + hh * 8 + lg;
            if (mod_ids[row] == m) {
                int c0 = hh * 2, c1 = hh * 2 + 1;
#pragma unroll
                for (int ni = 0; ni < 8; ++ni) {
                    int cl = ni * 8 + lt * 2;
                    float2 o = {d[mi][ni][c0], d[mi][ni][c1]};
                    *(float2*)(g_o + (size_t)row * kD + cols + wn * 64 + cl) = o;
                }
            }
        }
    }
}

// ---------------------------------------------------------------------------
// K5: final full-row RMSNorm (fp32)
// ---------------------------------------------------------------------------
__global__ __launch_bounds__(256) void k_rmsout(const int* __restrict__ mod_ids,
                                                const float* __restrict__ anw,
                                                float* __restrict__ out)
{
    const int rg = blockIdx.x;
    const int tid = threadIdx.x;
    const int mid = mod_ids[rg];
    const float* src = g_o + (size_t)rg * kD;

    float4 v = *(const float4*)(src + tid * 4);
    float ss = v.x * v.x + v.y * v.y + v.z * v.z + v.w * v.w;
#pragma unroll
    for (int off = 16; off > 0; off >>= 1)
        ss += __shfl_xor_sync(0xffffffffu, ss, off);

    __shared__ float red[8];
    __shared__ float scale_sh;
    if ((tid & 31) == 0) red[tid >> 5] = ss;
    __syncthreads();
    if (tid == 0) {
        float t = 0.0f;
#pragma unroll
        for (int w = 0; w < 8; ++w) t += red[w];
        scale_sh = rsqrtf(t * (1.0f / kD) + kEps);
    }
    __syncthreads();
    float sc = scale_sh;

    const float* w = anw + (size_t)mid * kD;
    float4 w4 = *(const float4*)(w + tid * 4);
    float4 o = {v.x * sc * w4.x, v.y * sc * w4.y, v.z * sc * w4.z, v.w * sc * w4.w};
    *(float4*)(out + (size_t)rg * kD + tid * 4) = o;
}

// ---------------------------------------------------------------------------
extern "C" void kernel_launch(void* const* d_in, const int* in_sizes, int n_in,
                              void* d_out, int out_size)
{
    const float* x         = (const float*)d_in[0];
    const float* attn_mask = (const float*)d_in[1];
    const int*   mod_ids   = (const int*)d_in[2];
    const float* Wq        = (const float*)d_in[3];
    const float* Wk        = (const float*)d_in[4];
    const float* Wv        = (const float*)d_in[5];
    const float* Wo        = (const float*)d_in[6];
    const float* qn_w      = (const float*)d_in[7];
    const float* kn_w      = (const float*)d_in[8];
    const float* anw       = (const float*)d_in[9];

    float* out = (float*)d_out;
    float* aw  = out + (size_t)kNR * kD;

    constexpr int kFlashSmem = 384 * 68 * 4;   // Qs+Ks+Vs+Ps = 104448 B
    constexpr int kAttnwSmem = 192 * 68 * 4;   // Qs+Ks = 52224 B
    cudaFuncSetAttribute(k_flash, cudaFuncAttributeMaxDynamicSharedMemorySize, kFlashSmem);
    cudaFuncSetAttribute(k_attnw, cudaFuncAttributeMaxDynamicSharedMemorySize, kAttnwSmem);

    dim3 blk(256);
    k_qkv  <<<dim3(kE / 128, kNR / 128, 6), blk>>>(x, Wq, Wk, Wv, mod_ids, qn_w, kn_w);
    k_flash<<<dim3(kS / 128, kB * kH), blk, kFlashSmem>>>(attn_mask);
    k_attnw<<<dim3(kS / 64, kS / 128, kB), blk, kAttnwSmem>>>(attn_mask, aw);
    k_oproj<<<dim3(kD / 128, kNR / 128, kM), blk>>>(Wo, mod_ids);
    k_rmsout<<<kNR, blk>>>(mod_ids, anw, out);
}

// round 4
// speedup vs baseline: 3.9888x; 1.1859x over previous
#include <cuda_runtime.h>
#include <cstdint>

// ---------------------------------------------------------------------------
// SimpleModalityUntiedAttention: B=2 S=2048 D=1024 H=16 HD=64 M=2 E=1024
// Round 4: tf32 mma path + modality compaction (gather rows per modality,
// run dense GEMM on ~half the tiles, scatter back). Removes the ~50% wasted
// FLOPs in qkv/oproj from compute-both-modalities-and-discard.
// ---------------------------------------------------------------------------

namespace {
constexpr int kB  = 2;
constexpr int kS  = 2048;
constexpr int kD  = 1024;
constexpr int kH  = 16;
constexpr int kHD = 64;
constexpr int kM  = 2;
constexpr int kE  = 1024;
constexpr int kNR = kB * kS;
constexpr float kEps   = 1e-5f;
constexpr float kScale = 0.125f;
}

__device__ float g_q[kNR * kE];
__device__ float g_k[kNR * kE];
__device__ float g_v[kNR * kE];
__device__ float g_ctx[kNR * kE];
__device__ float g_o[kNR * kD];
__device__ float g_ml[kB * kH * kS * 2];
__device__ int   g_idx[kM * kNR];   // compacted row index lists
__device__ int   g_cnt[kM];         // rows per modality

__device__ __forceinline__ float f2tf(float x) {
    uint32_t u;
    asm("cvt.rna.tf32.f32 %0, %1;" : "=r"(u) : "f"(x));
    return __uint_as_float(u);
}
__device__ __forceinline__ uint32_t fu(float x) { return __float_as_uint(x); }

__device__ __forceinline__ void mma_tf32(float* d, const uint32_t* a, const uint32_t* b) {
    asm volatile(
        "mma.sync.aligned.m16n8k8.row.col.f32.tf32.tf32.f32 "
        "{%0,%1,%2,%3}, {%4,%5,%6,%7}, {%8,%9}, {%0,%1,%2,%3};"
        : "+f"(d[0]), "+f"(d[1]), "+f"(d[2]), "+f"(d[3])
        : "r"(a[0]), "r"(a[1]), "r"(a[2]), "r"(a[3]), "r"(b[0]), "r"(b[1]));
}

// ---------------------------------------------------------------------------
// K0: modality compaction. Single block; ordering within a modality is
// arbitrary (atomics) but per-row outputs are order-independent.
// ---------------------------------------------------------------------------
__global__ __launch_bounds__(1024) void k_compact(const int* __restrict__ mod_ids)
{
    __shared__ int cnt[kM];
    const int tid = threadIdx.x;
    if (tid < kM) cnt[tid] = 0;
    __syncthreads();
    for (int r = tid; r < kNR; r += 1024) {
        int m = mod_ids[r];
        int pos = atomicAdd(&cnt[m], 1);
        g_idx[m * kNR + pos] = r;
    }
    __syncthreads();
    int c0 = cnt[0], c1 = cnt[1];
    if (tid == 0) { g_cnt[0] = c0; g_cnt[1] = c1; }
    // pad tails with a valid row (never stored for padded slots)
    for (int i = c0 + tid; i < kNR; i += 1024) g_idx[i] = 0;
    for (int i = c1 + tid; i < kNR; i += 1024) g_idx[kNR + i] = 0;
}

// ---------------------------------------------------------------------------
// K1: QKV projection over compacted rows. 128x128 block tile, tf32 mma,
// fused per-head RMSNorm (warp tile 32x64 spans exactly one head).
// grid = (8, 32, 6); z = m*3 + which; blocks beyond cnt[m] exit.
// ---------------------------------------------------------------------------
__global__ __launch_bounds__(256) void k_qkv(
    const float* __restrict__ x,
    const float* __restrict__ Wq, const float* __restrict__ Wk,
    const float* __restrict__ Wv,
    const float* __restrict__ qn_w, const float* __restrict__ kn_w)
{
    const int z = blockIdx.z;
    const int m = z / 3;
    const int which = z % 3;
    const int cnt = g_cnt[m];
    const int rows = blockIdx.y * 128;
    if (rows >= cnt) return;

    const float* W = ((which == 0) ? Wq : (which == 1) ? Wk : Wv) + (size_t)m * kD * kE;
    float* Cout = (which == 0) ? g_q : (which == 1) ? g_k : g_v;
    const int* idx = g_idx + m * kNR;

    const int tid = threadIdx.x;
    const int wid = tid >> 5, lane = tid & 31;
    const int lg = lane >> 2, lt = lane & 3;
    const int wm = wid & 3, wn = wid >> 2;
    const int cols = blockIdx.x * 128;

    __shared__ float As[128][20];
    __shared__ float Bs[16][136];

    float d[2][8][4] = {};

    const int ar0 = tid >> 2, ac0 = (tid & 3) << 2;
    const int bk0 = tid >> 5, bn0 = (tid & 31) << 2;
    const int orow0 = idx[rows + ar0];
    const int orow1 = idx[rows + ar0 + 64];

    for (int k0 = 0; k0 < kD; k0 += 16) {
        float4 av0 = *(const float4*)(x + (size_t)orow0 * kD + k0 + ac0);
        float4 av1 = *(const float4*)(x + (size_t)orow1 * kD + k0 + ac0);
        float4 bv0 = *(const float4*)(W + (size_t)(k0 + bk0) * kE + cols + bn0);
        float4 bv1 = *(const float4*)(W + (size_t)(k0 + bk0 + 8) * kE + cols + bn0);
        __syncthreads();
        {
            float4 t0 = {f2tf(av0.x), f2tf(av0.y), f2tf(av0.z), f2tf(av0.w)};
            float4 t1 = {f2tf(av1.x), f2tf(av1.y), f2tf(av1.z), f2tf(av1.w)};
            *(float4*)&As[ar0][ac0] = t0;
            *(float4*)&As[ar0 + 64][ac0] = t1;
            float4 u0 = {f2tf(bv0.x), f2tf(bv0.y), f2tf(bv0.z), f2tf(bv0.w)};
            float4 u1 = {f2tf(bv1.x), f2tf(bv1.y), f2tf(bv1.z), f2tf(bv1.w)};
            *(float4*)&Bs[bk0][bn0] = u0;
            *(float4*)&Bs[bk0 + 8][bn0] = u1;
        }
        __syncthreads();
#pragma unroll
        for (int ks = 0; ks < 16; ks += 8) {
            uint32_t a[2][4], b[8][2];
#pragma unroll
            for (int mi = 0; mi < 2; ++mi) {
                int r = wm * 32 + mi * 16 + lg;
                a[mi][0] = fu(As[r][ks + lt]);
                a[mi][1] = fu(As[r + 8][ks + lt]);
                a[mi][2] = fu(As[r][ks + 4 + lt]);
                a[mi][3] = fu(As[r + 8][ks + 4 + lt]);
            }
#pragma unroll
            for (int ni = 0; ni < 8; ++ni) {
                int n = wn * 64 + ni * 8 + lg;
                b[ni][0] = fu(Bs[ks + lt][n]);
                b[ni][1] = fu(Bs[ks + 4 + lt][n]);
            }
#pragma unroll
            for (int mi = 0; mi < 2; ++mi)
#pragma unroll
                for (int ni = 0; ni < 8; ++ni)
                    mma_tf32(d[mi][ni], a[mi], b[ni]);
        }
    }

    const float* wn_ptr = ((which == 0) ? qn_w : kn_w) + m * kHD;
#pragma unroll
    for (int mi = 0; mi < 2; ++mi) {
#pragma unroll
        for (int hh = 0; hh < 2; ++hh) {
            int iloc = rows + wm * 32 + mi * 16 + hh * 8 + lg;
            bool sel = (iloc < cnt);
            int row = idx[iloc];
            int c0 = hh * 2, c1 = hh * 2 + 1;
            if (which < 2) {
                float ss = 0.0f;
#pragma unroll
                for (int ni = 0; ni < 8; ++ni)
                    ss += d[mi][ni][c0] * d[mi][ni][c0] + d[mi][ni][c1] * d[mi][ni][c1];
                ss += __shfl_xor_sync(0xffffffffu, ss, 1);
                ss += __shfl_xor_sync(0xffffffffu, ss, 2);
                float sc = rsqrtf(ss * (1.0f / 64.0f) + kEps);
                if (sel) {
#pragma unroll
                    for (int ni = 0; ni < 8; ++ni) {
                        int cl = ni * 8 + lt * 2;
                        float2 o = {d[mi][ni][c0] * sc * wn_ptr[cl],
                                    d[mi][ni][c1] * sc * wn_ptr[cl + 1]};
                        *(float2*)(Cout + (size_t)row * kE + cols + wn * 64 + cl) = o;
                    }
                }
            } else if (sel) {
#pragma unroll
                for (int ni = 0; ni < 8; ++ni) {
                    int cl = ni * 8 + lt * 2;
                    float2 o = {d[mi][ni][c0], d[mi][ni][c1]};
                    *(float2*)(Cout + (size_t)row * kE + cols + wn * 64 + cl) = o;
                }
            }
        }
    }
}

// ---------------------------------------------------------------------------
// K2: flash attention, q-tile 128, k-tile 64, tf32 mma. Emits (m,l).
// ---------------------------------------------------------------------------
__global__ __launch_bounds__(256) void k_flash(const float* __restrict__ mask)
{
    extern __shared__ float sh[];
    float (*Qs)[68] = (float(*)[68])sh;
    float (*Ks)[68] = (float(*)[68])(sh + 128 * 68);
    float (*Vs)[68] = (float(*)[68])(sh + 192 * 68);
    float (*Ps)[68] = (float(*)[68])(sh + 256 * 68);

    const int bh = blockIdx.y;
    const int b = bh >> 4, h = bh & 15;
    const int qbase = blockIdx.x * 128;
    const int tid = threadIdx.x;
    const int wid = tid >> 5, lane = tid & 31;
    const int lg = lane >> 2, lt = lane & 3;
    const int r0 = wid * 16;

    {
        const float* qsrc = g_q + ((size_t)(b * kS + qbase)) * kE + h * kHD;
#pragma unroll
        for (int rr = 0; rr < 8; ++rr) {
            int idx = tid + rr * 256;
            int q = idx >> 4, d4 = (idx & 15) << 2;
            float4 v = *(const float4*)(qsrc + (size_t)q * kE + d4);
            float4 t = {f2tf(v.x), f2tf(v.y), f2tf(v.z), f2tf(v.w)};
            *(float4*)&Qs[q][d4] = t;
        }
    }

    float oacc[8][4] = {};
    float mr[2] = {-3e38f, -3e38f}, lr[2] = {0.0f, 0.0f};
    const int qrow0 = qbase + r0 + lg;
    const int qrow1 = qrow0 + 8;

    for (int kb = 0; kb < kS; kb += 64) {
        __syncthreads();
        {
            const float* ksrc = g_k + ((size_t)(b * kS + kb)) * kE + h * kHD;
            const float* vsrc = g_v + ((size_t)(b * kS + kb)) * kE + h * kHD;
#pragma unroll
            for (int rr = 0; rr < 4; ++rr) {
                int idx = tid + rr * 256;
                int kc = idx >> 4, d4 = (idx & 15) << 2;
                float4 v = *(const float4*)(ksrc + (size_t)kc * kE + d4);
                float4 t = {f2tf(v.x), f2tf(v.y), f2tf(v.z), f2tf(v.w)};
                *(float4*)&Ks[kc][d4] = t;
                float4 w = *(const float4*)(vsrc + (size_t)kc * kE + d4);
                Vs[d4 + 0][kc] = f2tf(w.x);
                Vs[d4 + 1][kc] = f2tf(w.y);
                Vs[d4 + 2][kc] = f2tf(w.z);
                Vs[d4 + 3][kc] = f2tf(w.w);
            }
        }
        __syncthreads();

        float s[8][4] = {};
#pragma unroll
        for (int ks = 0; ks < 64; ks += 8) {
            uint32_t a[4];
            a[0] = fu(Qs[r0 + lg][ks + lt]);
            a[1] = fu(Qs[r0 + 8 + lg][ks + lt]);
            a[2] = fu(Qs[r0 + lg][ks + 4 + lt]);
            a[3] = fu(Qs[r0 + 8 + lg][ks + 4 + lt]);
#pragma unroll
            for (int ni = 0; ni < 8; ++ni) {
                uint32_t bfr[2];
                bfr[0] = fu(Ks[ni * 8 + lg][ks + lt]);
                bfr[1] = fu(Ks[ni * 8 + lg][ks + 4 + lt]);
                mma_tf32(s[ni], a, bfr);
            }
        }

#pragma unroll
        for (int ni = 0; ni < 8; ++ni) {
            size_t col = (size_t)kb + ni * 8 + lt * 2;
            float2 m0 = *(const float2*)(mask + (size_t)qrow0 * kS + col);
            float2 m1 = *(const float2*)(mask + (size_t)qrow1 * kS + col);
            s[ni][0] = fmaf(s[ni][0], kScale, m0.x);
            s[ni][1] = fmaf(s[ni][1], kScale, m0.y);
            s[ni][2] = fmaf(s[ni][2], kScale, m1.x);
            s[ni][3] = fmaf(s[ni][3], kScale, m1.y);
        }

#pragma unroll
        for (int rp = 0; rp < 2; ++rp) {
            int i0 = rp * 2, i1 = rp * 2 + 1;
            float tm = -3e38f;
#pragma unroll
            for (int ni = 0; ni < 8; ++ni)
                tm = fmaxf(tm, fmaxf(s[ni][i0], s[ni][i1]));
            tm = fmaxf(tm, __shfl_xor_sync(0xffffffffu, tm, 1));
            tm = fmaxf(tm, __shfl_xor_sync(0xffffffffu, tm, 2));
            float nm = fmaxf(mr[rp], tm);
            float corr = __expf(mr[rp] - nm);
            float ps = 0.0f;
#pragma unroll
            for (int ni = 0; ni < 8; ++ni) {
                s[ni][i0] = __expf(s[ni][i0] - nm);
                s[ni][i1] = __expf(s[ni][i1] - nm);
                ps += s[ni][i0] + s[ni][i1];
            }
            ps += __shfl_xor_sync(0xffffffffu, ps, 1);
            ps += __shfl_xor_sync(0xffffffffu, ps, 2);
            lr[rp] = lr[rp] * corr + ps;
            mr[rp] = nm;
#pragma unroll
            for (int ni = 0; ni < 8; ++ni) {
                oacc[ni][i0] *= corr;
                oacc[ni][i1] *= corr;
            }
        }

#pragma unroll
        for (int ni = 0; ni < 8; ++ni) {
            int cl = ni * 8 + lt * 2;
            float2 p0 = {f2tf(s[ni][0]), f2tf(s[ni][1])};
            float2 p1 = {f2tf(s[ni][2]), f2tf(s[ni][3])};
            *(float2*)&Ps[r0 + lg][cl] = p0;
            *(float2*)&Ps[r0 + 8 + lg][cl] = p1;
        }
        __syncwarp();

#pragma unroll
        for (int ks = 0; ks < 64; ks += 8) {
            uint32_t a[4];
            a[0] = fu(Ps[r0 + lg][ks + lt]);
            a[1] = fu(Ps[r0 + 8 + lg][ks + lt]);
            a[2] = fu(Ps[r0 + lg][ks + 4 + lt]);
            a[3] = fu(Ps[r0 + 8 + lg][ks + 4 + lt]);
#pragma unroll
            for (int ni = 0; ni < 8; ++ni) {
                uint32_t bfr[2];
                bfr[0] = fu(Vs[ni * 8 + lg][ks + lt]);
                bfr[1] = fu(Vs[ni * 8 + lg][ks + 4 + lt]);
                mma_tf32(oacc[ni], a, bfr);
            }
        }
    }

    float il0 = 1.0f / lr[0], il1 = 1.0f / lr[1];
#pragma unroll
    for (int ni = 0; ni < 8; ++ni) {
        int cl = ni * 8 + lt * 2;
        float2 o0 = {oacc[ni][0] * il0, oacc[ni][1] * il0};
        float2 o1 = {oacc[ni][2] * il1, oacc[ni][3] * il1};
        *(float2*)(g_ctx + (size_t)(b * kS + qrow0) * kE + h * kHD + cl) = o0;
        *(float2*)(g_ctx + (size_t)(b * kS + qrow1) * kE + h * kHD + cl) = o1;
    }
    if (lt == 0) {
        size_t i0 = ((size_t)bh * kS + qrow0) * 2;
        size_t i1 = ((size_t)bh * kS + qrow1) * 2;
        g_ml[i0] = mr[0]; g_ml[i0 + 1] = lr[0];
        g_ml[i1] = mr[1]; g_ml[i1 + 1] = lr[1];
    }
}

// ---------------------------------------------------------------------------
// K3: attn_weights = mean_h softmax, block (b, q-tile 128, k-tile 64)
// ---------------------------------------------------------------------------
__global__ __launch_bounds__(256) void k_attnw(const float* __restrict__ mask,
                                               float* __restrict__ aw_out)
{
    extern __shared__ float sh[];
    float (*Qs)[68] = (float(*)[68])sh;
    float (*Ks)[68] = (float(*)[68])(sh + 128 * 68);

    const int b = blockIdx.z;
    const int qbase = blockIdx.y * 128;
    const int kbase = blockIdx.x * 64;
    const int tid = threadIdx.x;
    const int wid = tid >> 5, lane = tid & 31;
    const int lg = lane >> 2, lt = lane & 3;
    const int r0 = wid * 16;
    const int qrow0 = qbase + r0 + lg;
    const int qrow1 = qrow0 + 8;

    float mk[8][4];
#pragma unroll
    for (int ni = 0; ni < 8; ++ni) {
        size_t col = (size_t)kbase + ni * 8 + lt * 2;
        float2 m0 = *(const float2*)(mask + (size_t)qrow0 * kS + col);
        float2 m1 = *(const float2*)(mask + (size_t)qrow1 * kS + col);
        mk[ni][0] = m0.x; mk[ni][1] = m0.y;
        mk[ni][2] = m1.x; mk[ni][3] = m1.y;
    }

    float aw[8][4] = {};

    for (int h = 0; h < kH; ++h) {
        __syncthreads();
        {
            const float* qsrc = g_q + ((size_t)(b * kS + qbase)) * kE + h * kHD;
#pragma unroll
            for (int rr = 0; rr < 8; ++rr) {
                int idx = tid + rr * 256;
                int q = idx >> 4, d4 = (idx & 15) << 2;
                float4 v = *(const float4*)(qsrc + (size_t)q * kE + d4);
                float4 t = {f2tf(v.x), f2tf(v.y), f2tf(v.z), f2tf(v.w)};
                *(float4*)&Qs[q][d4] = t;
            }
            const float* ksrc = g_k + ((size_t)(b * kS + kbase)) * kE + h * kHD;
#pragma unroll
            for (int rr = 0; rr < 4; ++rr) {
                int idx = tid + rr * 256;
                int kc = idx >> 4, d4 = (idx & 15) << 2;
                float4 v = *(const float4*)(ksrc + (size_t)kc * kE + d4);
                float4 t = {f2tf(v.x), f2tf(v.y), f2tf(v.z), f2tf(v.w)};
                *(float4*)&Ks[kc][d4] = t;
            }
        }
        __syncthreads();

        float s[8][4] = {};
#pragma unroll
        for (int ks = 0; ks < 64; ks += 8) {
            uint32_t a[4];
            a[0] = fu(Qs[r0 + lg][ks + lt]);
            a[1] = fu(Qs[r0 + 8 + lg][ks + lt]);
            a[2] = fu(Qs[r0 + lg][ks + 4 + lt]);
            a[3] = fu(Qs[r0 + 8 + lg][ks + 4 + lt]);
#pragma unroll
            for (int ni = 0; ni < 8; ++ni) {
                uint32_t bfr[2];
                bfr[0] = fu(Ks[ni * 8 + lg][ks + lt]);
                bfr[1] = fu(Ks[ni * 8 + lg][ks + 4 + lt]);
                mma_tf32(s[ni], a, bfr);
            }
        }

        float2 ml0 = *(const float2*)&g_ml[((size_t)(b * kH + h) * kS + qrow0) * 2];
        float2 ml1 = *(const float2*)&g_ml[((size_t)(b * kH + h) * kS + qrow1) * 2];
        float mi0 = ml0.x, il0 = 1.0f / ml0.y;
        float mi1 = ml1.x, il1 = 1.0f / ml1.y;
#pragma unroll
        for (int ni = 0; ni < 8; ++ni) {
            aw[ni][0] += __expf(fmaf(s[ni][0], kScale, mk[ni][0]) - mi0) * il0;
            aw[ni][1] += __expf(fmaf(s[ni][1], kScale, mk[ni][1]) - mi0) * il0;
            aw[ni][2] += __expf(fmaf(s[ni][2], kScale, mk[ni][2]) - mi1) * il1;
            aw[ni][3] += __expf(fmaf(s[ni][3], kScale, mk[ni][3]) - mi1) * il1;
        }
    }

#pragma unroll
    for (int ni = 0; ni < 8; ++ni) {
        int col = kbase + ni * 8 + lt * 2;
        float2 o0 = {aw[ni][0] * (1.0f / kH), aw[ni][1] * (1.0f / kH)};
        float2 o1 = {aw[ni][2] * (1.0f / kH), aw[ni][3] * (1.0f / kH)};
        *(float2*)(aw_out + (size_t)b * kS * kS + (size_t)qrow0 * kS + col) = o0;
        *(float2*)(aw_out + (size_t)b * kS * kS + (size_t)qrow1 * kS + col) = o1;
    }
}

// ---------------------------------------------------------------------------
// K4: output projection over compacted rows, modality-scattered store.
// grid = (8, 32, 2); blocks beyond cnt[m] exit.
// ---------------------------------------------------------------------------
__global__ __launch_bounds__(256) void k_oproj(const float* __restrict__ Wo)
{
    const int m = blockIdx.z;
    const int cnt = g_cnt[m];
    const int rows = blockIdx.y * 128;
    if (rows >= cnt) return;

    const float* W = Wo + (size_t)m * kE * kD;
    const int* idx = g_idx + m * kNR;

    const int tid = threadIdx.x;
    const int wid = tid >> 5, lane = tid & 31;
    const int lg = lane >> 2, lt = lane & 3;
    const int wm = wid & 3, wn = wid >> 2;
    const int cols = blockIdx.x * 128;

    __shared__ float As[128][20];
    __shared__ float Bs[16][136];

    float d[2][8][4] = {};

    const int ar0 = tid >> 2, ac0 = (tid & 3) << 2;
    const int bk0 = tid >> 5, bn0 = (tid & 31) << 2;
    const int orow0 = idx[rows + ar0];
    const int orow1 = idx[rows + ar0 + 64];

    for (int k0 = 0; k0 < kE; k0 += 16) {
        float4 av0 = *(const float4*)(g_ctx + (size_t)orow0 * kE + k0 + ac0);
        float4 av1 = *(const float4*)(g_ctx + (size_t)orow1 * kE + k0 + ac0);
        float4 bv0 = *(const float4*)(W + (size_t)(k0 + bk0) * kD + cols + bn0);
        float4 bv1 = *(const float4*)(W + (size_t)(k0 + bk0 + 8) * kD + cols + bn0);
        __syncthreads();
        {
            float4 t0 = {f2tf(av0.x), f2tf(av0.y), f2tf(av0.z), f2tf(av0.w)};
            float4 t1 = {f2tf(av1.x), f2tf(av1.y), f2tf(av1.z), f2tf(av1.w)};
            *(float4*)&As[ar0][ac0] = t0;
            *(float4*)&As[ar0 + 64][ac0] = t1;
            float4 u0 = {f2tf(bv0.x), f2tf(bv0.y), f2tf(bv0.z), f2tf(bv0.w)};
            float4 u1 = {f2tf(bv1.x), f2tf(bv1.y), f2tf(bv1.z), f2tf(bv1.w)};
            *(float4*)&Bs[bk0][bn0] = u0;
            *(float4*)&Bs[bk0 + 8][bn0] = u1;
        }
        __syncthreads();
#pragma unroll
        for (int ks = 0; ks < 16; ks += 8) {
            uint32_t a[2][4], b[8][2];
#pragma unroll
            for (int mi = 0; mi < 2; ++mi) {
                int r = wm * 32 + mi * 16 + lg;
                a[mi][0] = fu(As[r][ks + lt]);
                a[mi][1] = fu(As[r + 8][ks + lt]);
                a[mi][2] = fu(As[r][ks + 4 + lt]);
                a[mi][3] = fu(As[r + 8][ks + 4 + lt]);
            }
#pragma unroll
            for (int ni = 0; ni < 8; ++ni) {
                int n = wn * 64 + ni * 8 + lg;
                b[ni][0] = fu(Bs[ks + lt][n]);
                b[ni][1] = fu(Bs[ks + 4 + lt][n]);
            }
#pragma unroll
            for (int mi = 0; mi < 2; ++mi)
#pragma unroll
                for (int ni = 0; ni < 8; ++ni)
                    mma_tf32(d[mi][ni], a[mi], b[ni]);
        }
    }

#pragma unroll
    for (int mi = 0; mi < 2; ++mi) {
#pragma unroll
        for (int hh = 0; hh < 2; ++hh) {
            int iloc = rows + wm * 32 + mi * 16 + hh * 8 + lg;
            if (iloc < cnt) {
                int row = idx[iloc];
                int c0 = hh * 2, c1 = hh * 2 + 1;
#pragma unroll
                for (int ni = 0; ni < 8; ++ni) {
                    int cl = ni * 8 + lt * 2;
                    float2 o = {d[mi][ni][c0], d[mi][ni][c1]};
                    *(float2*)(g_o + (size_t)row * kD + cols + wn * 64 + cl) = o;
                }
            }
        }
    }
}

// ---------------------------------------------------------------------------
// K5: final full-row RMSNorm (fp32)
// ---------------------------------------------------------------------------
__global__ __launch_bounds__(256) void k_rmsout(const int* __restrict__ mod_ids,
                                                const float* __restrict__ anw,
                                                float* __restrict__ out)
{
    const int rg = blockIdx.x;
    const int tid = threadIdx.x;
    const int mid = mod_ids[rg];
    const float* src = g_o + (size_t)rg * kD;

    float4 v = *(const float4*)(src + tid * 4);
    float ss = v.x * v.x + v.y * v.y + v.z * v.z + v.w * v.w;
#pragma unroll
    for (int off = 16; off > 0; off >>= 1)
        ss += __shfl_xor_sync(0xffffffffu, ss, off);

    __shared__ float red[8];
    __shared__ float scale_sh;
    if ((tid & 31) == 0) red[tid >> 5] = ss;
    __syncthreads();
    if (tid == 0) {
        float t = 0.0f;
#pragma unroll
        for (int w = 0; w < 8; ++w) t += red[w];
        scale_sh = rsqrtf(t * (1.0f / kD) + kEps);
    }
    __syncthreads();
    float sc = scale_sh;

    const float* w = anw + (size_t)mid * kD;
    float4 w4 = *(const float4*)(w + tid * 4);
    float4 o = {v.x * sc * w4.x, v.y * sc * w4.y, v.z * sc * w4.z, v.w * sc * w4.w};
    *(float4*)(out + (size_t)rg * kD + tid * 4) = o;
}

// ---------------------------------------------------------------------------
extern "C" void kernel_launch(void* const* d_in, const int* in_sizes, int n_in,
                              void* d_out, int out_size)
{
    const float* x         = (const float*)d_in[0];
    const float* attn_mask = (const float*)d_in[1];
    const int*   mod_ids   = (const int*)d_in[2];
    const float* Wq        = (const float*)d_in[3];
    const float* Wk        = (const float*)d_in[4];
    const float* Wv        = (const float*)d_in[5];
    const float* Wo        = (const float*)d_in[6];
    const float* qn_w      = (const float*)d_in[7];
    const float* kn_w      = (const float*)d_in[8];
    const float* anw       = (const float*)d_in[9];

    float* out = (float*)d_out;
    float* aw  = out + (size_t)kNR * kD;

    constexpr int kFlashSmem = 384 * 68 * 4;
    constexpr int kAttnwSmem = 192 * 68 * 4;
    cudaFuncSetAttribute(k_flash, cudaFuncAttributeMaxDynamicSharedMemorySize, kFlashSmem);
    cudaFuncSetAttribute(k_attnw, cudaFuncAttributeMaxDynamicSharedMemorySize, kAttnwSmem);

    dim3 blk(256);
    k_compact<<<1, 1024>>>(mod_ids);
    k_qkv  <<<dim3(kE / 128, kNR / 128, 6), blk>>>(x, Wq, Wk, Wv, qn_w, kn_w);
    k_flash<<<dim3(kS / 128, kB * kH), blk, kFlashSmem>>>(attn_mask);
    k_attnw<<<dim3(kS / 64, kS / 128, kB), blk, kAttnwSmem>>>(attn_mask, aw);
    k_oproj<<<dim3(kD / 128, kNR / 128, kM), blk>>>(Wo);
    k_rmsout<<<kNR, blk>>>(mod_ids, anw, out);
}